// round 8
// baseline (speedup 1.0000x reference)
#include <cuda_runtime.h>

typedef unsigned long long u64;
#define DI __device__ __forceinline__

// Fixed average-trace buffer (length 120) from the reference module
__constant__ float c_avg[120] = {
 0.0256f,0.0823f,0.1157f,0.1315f,0.1366f,0.1369f,0.1347f,0.1308f,0.1259f,0.1205f,
 0.1146f,0.1086f,0.1028f,0.0970f,0.0913f,0.0858f,0.0805f,0.0756f,0.0708f,0.0664f,
 0.0623f,0.0584f,0.0549f,0.0515f,0.0485f,0.0456f,0.0429f,0.0404f,0.0381f,0.0360f,
 0.0340f,0.0321f,0.0304f,0.0287f,0.0272f,0.0258f,0.0245f,0.0233f,0.0222f,0.0211f,
 0.0201f,0.0191f,0.0182f,0.0173f,0.0165f,0.0158f,0.0150f,0.0143f,0.0137f,0.0130f,
 0.0125f,0.0119f,0.0114f,0.0108f,0.0104f,0.0099f,0.0095f,0.0091f,0.0087f,0.0083f,
 0.0080f,0.0077f,0.0074f,0.0071f,0.0068f,0.0065f,0.0062f,0.0060f,0.0058f,0.0055f,
 0.0053f,0.0050f,0.0049f,0.0047f,0.0045f,0.0044f,0.0042f,0.0040f,0.0039f,0.0038f,
 0.0036f,0.0034f,0.0033f,0.0032f,0.0031f,0.0030f,0.0029f,0.0028f,0.0027f,0.0026f,
 0.0025f,0.0024f,0.0023f,0.0022f,0.0021f,0.0021f,0.0020f,0.0019f,0.0018f,0.0018f,
 0.0017f,0.0017f,0.0016f,0.0016f,0.0015f,0.0015f,0.0014f,0.0014f,0.0013f,0.0013f,
 0.0013f,0.0012f,0.0012f,0.0011f,0.0011f,0.0011f,0.0010f,0.0010f,0.0010f,0.0009f
};

DI u64 pk2(float lo, float hi){ u64 r; asm("mov.b64 %0, {%1,%2};" : "=l"(r) : "f"(lo), "f"(hi)); return r; }
DI void up2(u64 v, float& lo, float& hi){ asm("mov.b64 {%0,%1}, %2;" : "=f"(lo), "=f"(hi) : "l"(v)); }
DI u64 ffma2(u64 a, u64 b, u64 c){ u64 d; asm("fma.rn.f32x2 %0, %1, %2, %3;" : "=l"(d) : "l"(a), "l"(b), "l"(c)); return d; }
DI float hadd2(u64 v){ float lo, hi; up2(v, lo, hi); return lo + hi; }
// Single-MUFU tanh. sigmoid pre-halved: sig = 0.5 + 0.5*tanh(x/2), /2 folded into weights.
DI float tanhfast(float x){ float y; asm("tanh.approx.f32 %0, %1;" : "=f"(y) : "f"(x)); return y; }
DI float sig_h(float xh){ return fmaf(tanhfast(xh), 0.5f, 0.5f); }

// Shared memory layout (bytes). 128 seqs per block, 2 threads per 2 seqs
// (thread-pair (2p,2p+1) handles seqs p and p+64; half=tid&1 selects even/odd units).
// i/f/o-gate rows PRE-SCALED by 0.5; g-gate unscaled.
#define OFF_WIF   0        // ulonglong2 wIF[30][15]   : 7200  ({i,f} k-pairs, x0.5)
#define OFF_WGO   7200     // ulonglong2 wGO[30][15]   : 7200  ({g,o}: g x1, o x0.5)
#define OFF_W13   14400    // float4 w13S[15][2]       : 480
#define OFF_W2    14880    // u64 w2S[4][15]           : 480
#define OFF_BASEA 15360    // float4 baseA[15][128]    : 30720 (seq p)
#define OFF_BASEB 46080    // float4 baseB[15][128]    : 30720 (seq p+64)
#define SMEM_BYTES 76800

__global__ __launch_bounds__(128, 2)
void lstm_trace_kernel(const float* __restrict__ features,
                       const float* __restrict__ w_ih1,
                       const float* __restrict__ w_hh1,
                       const float* __restrict__ b1,
                       const float* __restrict__ w_ih2,
                       const float* __restrict__ w_hh2,
                       const float* __restrict__ b2,
                       float* __restrict__ out)
{
    extern __shared__ char smraw[];
    ulonglong2* wIF   = (ulonglong2*)(smraw + OFF_WIF);
    ulonglong2* wGO   = (ulonglong2*)(smraw + OFF_WGO);
    float4*     w13S  = (float4*)    (smraw + OFF_W13);
    u64*        w2S   = (u64*)       (smraw + OFF_W2);
    float4*     baseA = (float4*)    (smraw + OFF_BASEA);
    float4*     baseB = (float4*)    (smraw + OFF_BASEB);

    const int tid  = threadIdx.x;
    const int half = tid & 1;                    // 0: even units, 1: odd units
    const int pair = tid >> 1;                   // 0..63
    const int seqA = blockIdx.x * 128 + pair;
    const int seqB = seqA + 64;

    // ---- stage recurrent weight tables (k-packed pairs, sigmoid gates x0.5) ----
    for (int e = tid; e < 450; e += 128){
        int r  = e / 15, k2 = e % 15;
        int u  = (r < 15) ? 2*r : 2*(r-15) + 1;
        int c0 = 2*k2, c1 = 2*k2 + 1;
        ulonglong2 a, b;
        a.x = pk2(0.5f*w_hh1[      u *30 + c0], 0.5f*w_hh1[      u *30 + c1]);  // i
        a.y = pk2(0.5f*w_hh1[(30 + u)*30 + c0], 0.5f*w_hh1[(30 + u)*30 + c1]);  // f
        b.x = pk2(      w_hh1[(60 + u)*30 + c0],      w_hh1[(60 + u)*30 + c1]); // g
        b.y = pk2(0.5f*w_hh1[(90 + u)*30 + c0], 0.5f*w_hh1[(90 + u)*30 + c1]);  // o
        wIF[e] = a; wGO[e] = b;
    }
    if (tid < 30){
        int j = tid >> 1, hh = tid & 1, u = 2*j + hh;
        float4 v;
        v.x = 0.5f*w_ih1[      u *13 + 12];
        v.y = 0.5f*w_ih1[(30 + u)*13 + 12];
        v.z =       w_ih1[(60 + u)*13 + 12];
        v.w = 0.5f*w_ih1[(90 + u)*13 + 12];
        w13S[j*2 + hh] = v;
    }
    if (tid < 60){
        int g = tid / 15, k2 = tid % 15;
        float s = (g == 2) ? 1.0f : 0.5f;
        w2S[tid] = pk2(s*w_ih2[g*30 + 2*k2], s*w_ih2[g*30 + 2*k2 + 1]);
    }

    // ---- per-thread time-invariant bases (own 15 units x 4 gates, both seqs) ----
    #pragma unroll
    for (int sb = 0; sb < 2; sb++){
        int seq = sb ? seqB : seqA;
        float4* baseS = sb ? baseB : baseA;
        float f[12];
        const float4* fp = reinterpret_cast<const float4*>(features) + (size_t)seq * 3;
        float4 fa = fp[0], fb = fp[1], fc = fp[2];
        f[0]=fa.x; f[1]=fa.y; f[2]=fa.z; f[3]=fa.w;
        f[4]=fb.x; f[5]=fb.y; f[6]=fb.z; f[7]=fb.w;
        f[8]=fc.x; f[9]=fc.y; f[10]=fc.z; f[11]=fc.w;
        #pragma unroll
        for (int j = 0; j < 15; j++){
            int u = 2*j + half;
            float4 bs;
            float* bsv = &bs.x;
            #pragma unroll
            for (int g = 0; g < 4; g++){
                int row = g*30 + u;
                float s = __ldg(&b1[row]);
                #pragma unroll
                for (int ff = 0; ff < 12; ff++)
                    s = fmaf(__ldg(&w_ih1[row*13 + ff]), f[ff], s);
                bsv[g] = (g == 2) ? s : 0.5f*s;
            }
            baseS[j*128 + tid] = bs;
        }
    }
    __syncthreads();

    // ---- per-thread recurrent state (two sequences) ----
    u64   hpkA[15], hpkB[15];     // (h[2j], h[2j+1]) full layer-1 h per seq
    float c1A[15],  c1B[15];      // cell state for OWN 15 units per seq
    #pragma unroll
    for (int j = 0; j < 15; j++){
        hpkA[j] = 0ull; hpkB[j] = 0ull; c1A[j] = 0.0f; c1B[j] = 0.0f;
    }
    // layer-2 state: each thread of the pair owns ONE sequence's layer 2
    float h2 = 0.0f, c2 = 0.0f;
    const float b2r0 = 0.5f*b2[0], b2r1 = 0.5f*b2[1], b2r2 = b2[2], b2r3 = 0.5f*b2[3];
    const float wh20 = 0.5f*w_hh2[0], wh21 = 0.5f*w_hh2[1], wh22 = w_hh2[2], wh23 = 0.5f*w_hh2[3];
    float* myOut = out + (size_t)(half ? seqB : seqA) * 120;

    const ulonglong2* myWIF  = wIF + (half*15) * 15;
    const ulonglong2* myWGO  = wGO + (half*15) * 15;
    const float4*     myBA   = baseA + tid;
    const float4*     myBB   = baseB + tid;
    const float4*     myW13  = w13S + half;

    // ---- time recurrence ----
    #pragma unroll 1
    for (int t = 0; t < 120; t++){
        const float av = c_avg[t];
        float nhA[15], nhB[15];

        #pragma unroll 5
        for (int j = 0; j < 15; j++){
            const ulonglong2* wif = myWIF + j*15;
            const ulonglong2* wgo = myWGO + j*15;
            float4 bsA = myBA[j*128];
            float4 bsB = myBB[j*128];
            float4 w13 = myW13[j*2];
            float wx = w13.x*av, wy = w13.y*av, wz = w13.z*av, ww = w13.w*av;
            u64 aiA = pk2(bsA.x, wx), afA = pk2(bsA.y, wy);
            u64 agA = pk2(bsA.z, wz), aoA = pk2(bsA.w, ww);
            u64 aiB = pk2(bsB.x, wx), afB = pk2(bsB.y, wy);
            u64 agB = pk2(bsB.z, wz), aoB = pk2(bsB.w, ww);
            #pragma unroll
            for (int k2 = 0; k2 < 15; k2++){
                ulonglong2 a = wif[k2], b = wgo[k2];
                u64 hA = hpkA[k2], hB = hpkB[k2];
                aiA = ffma2(a.x, hA, aiA); afA = ffma2(a.y, hA, afA);
                agA = ffma2(b.x, hA, agA); aoA = ffma2(b.y, hA, aoA);
                aiB = ffma2(a.x, hB, aiB); afB = ffma2(a.y, hB, afB);
                agB = ffma2(b.x, hB, agB); aoB = ffma2(b.y, hB, aoB);
            }
            {
                float si = sig_h(hadd2(aiA));
                float sf = sig_h(hadd2(afA));
                float tg = tanhfast(hadd2(agA));
                float so = sig_h(hadd2(aoA));
                float cc = fmaf(sf, c1A[j], si*tg);
                c1A[j] = cc;
                nhA[j] = so * tanhfast(cc);
            }
            {
                float si = sig_h(hadd2(aiB));
                float sf = sig_h(hadd2(afB));
                float tg = tanhfast(hadd2(agB));
                float so = sig_h(hadd2(aoB));
                float cc = fmaf(sf, c1B[j], si*tg);
                c1B[j] = cc;
                nhB[j] = so * tanhfast(cc);
            }
        }

        // exchange new h with partner thread, repack as (even, odd) pairs
        #pragma unroll
        for (int j = 0; j < 15; j++){
            float oA = __shfl_xor_sync(0xFFFFFFFFu, nhA[j], 1);
            float oB = __shfl_xor_sync(0xFFFFFFFFu, nhB[j], 1);
            hpkA[j] = half ? pk2(oA, nhA[j]) : pk2(nhA[j], oA);
            hpkB[j] = half ? pk2(oB, nhB[j]) : pk2(nhB[j], oB);
        }

        // layer 2: this thread handles ONE sequence (half==0 -> A, half==1 -> B)
        u64 a0 = pk2(b2r0, wh20*h2);
        u64 a1 = pk2(b2r1, wh21*h2);
        u64 a2 = pk2(b2r2, wh22*h2);
        u64 a3 = pk2(b2r3, wh23*h2);
        if (half){
            #pragma unroll
            for (int k2 = 0; k2 < 15; k2++){
                u64 h = hpkB[k2];
                a0 = ffma2(w2S[k2],      h, a0);
                a1 = ffma2(w2S[15 + k2], h, a1);
                a2 = ffma2(w2S[30 + k2], h, a2);
                a3 = ffma2(w2S[45 + k2], h, a3);
            }
        } else {
            #pragma unroll
            for (int k2 = 0; k2 < 15; k2++){
                u64 h = hpkA[k2];
                a0 = ffma2(w2S[k2],      h, a0);
                a1 = ffma2(w2S[15 + k2], h, a1);
                a2 = ffma2(w2S[30 + k2], h, a2);
                a3 = ffma2(w2S[45 + k2], h, a3);
            }
        }
        float si2 = sig_h(hadd2(a0));
        float sf2 = sig_h(hadd2(a1));
        float tg2 = tanhfast(hadd2(a2));
        float so2 = sig_h(hadd2(a3));
        c2 = fmaf(sf2, c2, si2*tg2);
        h2 = so2 * tanhfast(c2);

        myOut[t] = h2;
    }
}

extern "C" void kernel_launch(void* const* d_in, const int* in_sizes, int n_in,
                              void* d_out, int out_size)
{
    const float* features = (const float*)d_in[0];
    const float* w_ih1    = (const float*)d_in[1];
    const float* w_hh1    = (const float*)d_in[2];
    const float* b1       = (const float*)d_in[3];
    const float* w_ih2    = (const float*)d_in[4];
    const float* w_hh2    = (const float*)d_in[5];
    const float* b2       = (const float*)d_in[6];
    float* out = (float*)d_out;

    cudaFuncSetAttribute(lstm_trace_kernel,
                         cudaFuncAttributeMaxDynamicSharedMemorySize, SMEM_BYTES);
    lstm_trace_kernel<<<256, 128, SMEM_BYTES>>>(features, w_ih1, w_hh1, b1,
                                                w_ih2, w_hh2, b2, out);
}

// round 10
// speedup vs baseline: 1.5830x; 1.5830x over previous
#include <cuda_runtime.h>

typedef unsigned long long u64;
#define DI __device__ __forceinline__

// Fixed average-trace buffer (length 120) from the reference module
__constant__ float c_avg[120] = {
 0.0256f,0.0823f,0.1157f,0.1315f,0.1366f,0.1369f,0.1347f,0.1308f,0.1259f,0.1205f,
 0.1146f,0.1086f,0.1028f,0.0970f,0.0913f,0.0858f,0.0805f,0.0756f,0.0708f,0.0664f,
 0.0623f,0.0584f,0.0549f,0.0515f,0.0485f,0.0456f,0.0429f,0.0404f,0.0381f,0.0360f,
 0.0340f,0.0321f,0.0304f,0.0287f,0.0272f,0.0258f,0.0245f,0.0233f,0.0222f,0.0211f,
 0.0201f,0.0191f,0.0182f,0.0173f,0.0165f,0.0158f,0.0150f,0.0143f,0.0137f,0.0130f,
 0.0125f,0.0119f,0.0114f,0.0108f,0.0104f,0.0099f,0.0095f,0.0091f,0.0087f,0.0083f,
 0.0080f,0.0077f,0.0074f,0.0071f,0.0068f,0.0065f,0.0062f,0.0060f,0.0058f,0.0055f,
 0.0053f,0.0050f,0.0049f,0.0047f,0.0045f,0.0044f,0.0042f,0.0040f,0.0039f,0.0038f,
 0.0036f,0.0034f,0.0033f,0.0032f,0.0031f,0.0030f,0.0029f,0.0028f,0.0027f,0.0026f,
 0.0025f,0.0024f,0.0023f,0.0022f,0.0021f,0.0021f,0.0020f,0.0019f,0.0018f,0.0018f,
 0.0017f,0.0017f,0.0016f,0.0016f,0.0015f,0.0015f,0.0014f,0.0014f,0.0013f,0.0013f,
 0.0013f,0.0012f,0.0012f,0.0011f,0.0011f,0.0011f,0.0010f,0.0010f,0.0010f,0.0009f
};

DI u64 pk2(float lo, float hi){ u64 r; asm("mov.b64 %0, {%1,%2};" : "=l"(r) : "f"(lo), "f"(hi)); return r; }
DI void up2(u64 v, float& lo, float& hi){ asm("mov.b64 {%0,%1}, %2;" : "=f"(lo), "=f"(hi) : "l"(v)); }
DI u64 ffma2(u64 a, u64 b, u64 c){ u64 d; asm("fma.rn.f32x2 %0, %1, %2, %3;" : "=l"(d) : "l"(a), "l"(b), "l"(c)); return d; }
DI float hadd2(u64 v){ float lo, hi; up2(v, lo, hi); return lo + hi; }
// Single-MUFU tanh. sigmoid pre-halved: sig = 0.5 + 0.5*tanh(x/2), /2 folded into weights.
DI float tanhfast(float x){ float y; asm("tanh.approx.f32 %0, %1;" : "=f"(y) : "f"(x)); return y; }
DI float sig_h(float xh){ return fmaf(tanhfast(xh), 0.5f, 0.5f); }

// Shared memory layout (bytes). 128 seqs per block, thread-pair (2p,2p+1) handles
// seqs p and p+64; half=tid&1 selects even/odd units of BOTH sequences.
// i/f/o-gate rows PRE-SCALED by 0.5; g-gate unscaled.
#define OFF_WIF   0        // ulonglong2 wIF[30][15]   : 7200  ({i,f} k-pairs, x0.5)
#define OFF_WGO   7200     // ulonglong2 wGO[30][15]   : 7200  ({g,o}: g x1, o x0.5)
#define OFF_W13   14400    // float4 w13S[15][2]       : 480
#define OFF_W2    14880    // u64 w2S[4][15]           : 480
#define OFF_BASEA 15360    // float4 baseA[15][128]    : 30720 (seq p)
#define OFF_BASEB 46080    // float4 baseB[15][128]    : 30720 (seq p+64)
#define SMEM_BYTES 76800

__global__ __launch_bounds__(128, 2)
void lstm_trace_kernel(const float* __restrict__ features,
                       const float* __restrict__ w_ih1,
                       const float* __restrict__ w_hh1,
                       const float* __restrict__ b1,
                       const float* __restrict__ w_ih2,
                       const float* __restrict__ w_hh2,
                       const float* __restrict__ b2,
                       float* __restrict__ out)
{
    extern __shared__ char smraw[];
    ulonglong2* wIF   = (ulonglong2*)(smraw + OFF_WIF);
    ulonglong2* wGO   = (ulonglong2*)(smraw + OFF_WGO);
    float4*     w13S  = (float4*)    (smraw + OFF_W13);
    u64*        w2S   = (u64*)       (smraw + OFF_W2);
    float4*     baseA = (float4*)    (smraw + OFF_BASEA);
    float4*     baseB = (float4*)    (smraw + OFF_BASEB);

    const int tid  = threadIdx.x;
    const int half = tid & 1;                    // 0: even units, 1: odd units
    const int pair = tid >> 1;                   // 0..63
    const int seqA = blockIdx.x * 128 + pair;
    const int seqB = seqA + 64;

    // ---- stage recurrent weight tables (k-packed pairs, sigmoid gates x0.5) ----
    for (int e = tid; e < 450; e += 128){
        int r  = e / 15, k2 = e % 15;
        int u  = (r < 15) ? 2*r : 2*(r-15) + 1;
        int c0 = 2*k2, c1 = 2*k2 + 1;
        ulonglong2 a, b;
        a.x = pk2(0.5f*w_hh1[      u *30 + c0], 0.5f*w_hh1[      u *30 + c1]);  // i
        a.y = pk2(0.5f*w_hh1[(30 + u)*30 + c0], 0.5f*w_hh1[(30 + u)*30 + c1]);  // f
        b.x = pk2(      w_hh1[(60 + u)*30 + c0],      w_hh1[(60 + u)*30 + c1]); // g
        b.y = pk2(0.5f*w_hh1[(90 + u)*30 + c0], 0.5f*w_hh1[(90 + u)*30 + c1]);  // o
        wIF[e] = a; wGO[e] = b;
    }
    if (tid < 30){
        int j = tid >> 1, hh = tid & 1, u = 2*j + hh;
        float4 v;
        v.x = 0.5f*w_ih1[      u *13 + 12];
        v.y = 0.5f*w_ih1[(30 + u)*13 + 12];
        v.z =       w_ih1[(60 + u)*13 + 12];
        v.w = 0.5f*w_ih1[(90 + u)*13 + 12];
        w13S[j*2 + hh] = v;
    }
    if (tid < 60){
        int g = tid / 15, k2 = tid % 15;
        float s = (g == 2) ? 1.0f : 0.5f;
        w2S[tid] = pk2(s*w_ih2[g*30 + 2*k2], s*w_ih2[g*30 + 2*k2 + 1]);
    }

    // ---- per-thread time-invariant bases (own 15 units x 4 gates, both seqs) ----
    #pragma unroll
    for (int sb = 0; sb < 2; sb++){
        int seq = sb ? seqB : seqA;
        float4* baseS = sb ? baseB : baseA;
        float f[12];
        const float4* fp = reinterpret_cast<const float4*>(features) + (size_t)seq * 3;
        float4 fa = fp[0], fb = fp[1], fc = fp[2];
        f[0]=fa.x; f[1]=fa.y; f[2]=fa.z; f[3]=fa.w;
        f[4]=fb.x; f[5]=fb.y; f[6]=fb.z; f[7]=fb.w;
        f[8]=fc.x; f[9]=fc.y; f[10]=fc.z; f[11]=fc.w;
        #pragma unroll 1
        for (int j = 0; j < 15; j++){
            int u = 2*j + half;
            float4 bs;
            float* bsv = &bs.x;
            #pragma unroll
            for (int g = 0; g < 4; g++){
                int row = g*30 + u;
                float s = __ldg(&b1[row]);
                #pragma unroll
                for (int ff = 0; ff < 12; ff++)
                    s = fmaf(__ldg(&w_ih1[row*13 + ff]), f[ff], s);
                bsv[g] = (g == 2) ? s : 0.5f*s;
            }
            baseS[j*128 + tid] = bs;
        }
    }
    __syncthreads();

    // ---- per-thread recurrent state (two sequences) ----
    u64   hpkA[15], hpkB[15];     // (h[2j], h[2j+1]) full layer-1 h per seq
    float c1A[15],  c1B[15];      // cell state for OWN 15 units per seq
    #pragma unroll
    for (int j = 0; j < 15; j++){
        hpkA[j] = 0ull; hpkB[j] = 0ull; c1A[j] = 0.0f; c1B[j] = 0.0f;
    }
    // layer-2 state: each thread of the pair owns ONE sequence's layer 2
    float h2 = 0.0f, c2 = 0.0f;
    const float b2r0 = 0.5f*b2[0], b2r1 = 0.5f*b2[1], b2r2 = b2[2], b2r3 = 0.5f*b2[3];
    const float wh20 = 0.5f*w_hh2[0], wh21 = 0.5f*w_hh2[1], wh22 = w_hh2[2], wh23 = 0.5f*w_hh2[3];
    float* myOut = out + (size_t)(half ? seqB : seqA) * 120;

    const ulonglong2* myWIF  = wIF + (half*15) * 15;
    const ulonglong2* myWGO  = wGO + (half*15) * 15;
    const float4*     myBA   = baseA + tid;
    const float4*     myBB   = baseB + tid;
    const float4*     myW13  = w13S + half;

    // ---- time recurrence ----
    #pragma unroll 1
    for (int t = 0; t < 120; t++){
        const float av = c_avg[t];
        float nhA[15], nhB[15];

        // unroll 2: bounded live accumulator set (16 u64) + LDS prefetch window
        #pragma unroll 2
        for (int j = 0; j < 15; j++){
            const ulonglong2* wif = myWIF + j*15;
            const ulonglong2* wgo = myWGO + j*15;
            float4 bsA = myBA[j*128];
            float4 bsB = myBB[j*128];
            float4 w13 = myW13[j*2];
            float wx = w13.x*av, wy = w13.y*av, wz = w13.z*av, ww = w13.w*av;
            u64 aiA = pk2(bsA.x, wx), afA = pk2(bsA.y, wy);
            u64 agA = pk2(bsA.z, wz), aoA = pk2(bsA.w, ww);
            u64 aiB = pk2(bsB.x, wx), afB = pk2(bsB.y, wy);
            u64 agB = pk2(bsB.z, wz), aoB = pk2(bsB.w, ww);
            #pragma unroll
            for (int k2 = 0; k2 < 15; k2++){
                ulonglong2 a = wif[k2], b = wgo[k2];
                u64 hA = hpkA[k2], hB = hpkB[k2];
                aiA = ffma2(a.x, hA, aiA); afA = ffma2(a.y, hA, afA);
                agA = ffma2(b.x, hA, agA); aoA = ffma2(b.y, hA, aoA);
                aiB = ffma2(a.x, hB, aiB); afB = ffma2(a.y, hB, afB);
                agB = ffma2(b.x, hB, agB); aoB = ffma2(b.y, hB, aoB);
            }
            {
                float si = sig_h(hadd2(aiA));
                float sf = sig_h(hadd2(afA));
                float tg = tanhfast(hadd2(agA));
                float so = sig_h(hadd2(aoA));
                float cc = fmaf(sf, c1A[j], si*tg);
                c1A[j] = cc;
                nhA[j] = so * tanhfast(cc);
            }
            {
                float si = sig_h(hadd2(aiB));
                float sf = sig_h(hadd2(afB));
                float tg = tanhfast(hadd2(agB));
                float so = sig_h(hadd2(aoB));
                float cc = fmaf(sf, c1B[j], si*tg);
                c1B[j] = cc;
                nhB[j] = so * tanhfast(cc);
            }
        }

        // exchange new h with partner thread, repack as (even, odd) pairs
        #pragma unroll
        for (int j = 0; j < 15; j++){
            float oA = __shfl_xor_sync(0xFFFFFFFFu, nhA[j], 1);
            float oB = __shfl_xor_sync(0xFFFFFFFFu, nhB[j], 1);
            hpkA[j] = half ? pk2(oA, nhA[j]) : pk2(nhA[j], oA);
            hpkB[j] = half ? pk2(oB, nhB[j]) : pk2(nhB[j], oB);
        }

        // layer 2: this thread handles ONE sequence (half==0 -> A, half==1 -> B)
        u64 a0 = pk2(b2r0, wh20*h2);
        u64 a1 = pk2(b2r1, wh21*h2);
        u64 a2 = pk2(b2r2, wh22*h2);
        u64 a3 = pk2(b2r3, wh23*h2);
        #pragma unroll
        for (int k2 = 0; k2 < 15; k2++){
            u64 h = half ? hpkB[k2] : hpkA[k2];
            a0 = ffma2(w2S[k2],      h, a0);
            a1 = ffma2(w2S[15 + k2], h, a1);
            a2 = ffma2(w2S[30 + k2], h, a2);
            a3 = ffma2(w2S[45 + k2], h, a3);
        }
        float si2 = sig_h(hadd2(a0));
        float sf2 = sig_h(hadd2(a1));
        float tg2 = tanhfast(hadd2(a2));
        float so2 = sig_h(hadd2(a3));
        c2 = fmaf(sf2, c2, si2*tg2);
        h2 = so2 * tanhfast(c2);

        myOut[t] = h2;
    }
}

extern "C" void kernel_launch(void* const* d_in, const int* in_sizes, int n_in,
                              void* d_out, int out_size)
{
    const float* features = (const float*)d_in[0];
    const float* w_ih1    = (const float*)d_in[1];
    const float* w_hh1    = (const float*)d_in[2];
    const float* b1       = (const float*)d_in[3];
    const float* w_ih2    = (const float*)d_in[4];
    const float* w_hh2    = (const float*)d_in[5];
    const float* b2       = (const float*)d_in[6];
    float* out = (float*)d_out;

    cudaFuncSetAttribute(lstm_trace_kernel,
                         cudaFuncAttributeMaxDynamicSharedMemorySize, SMEM_BYTES);
    lstm_trace_kernel<<<256, 128, SMEM_BYTES>>>(features, w_ih1, w_hh1, b1,
                                                w_ih2, w_hh2, b2, out);
}

// round 11
// speedup vs baseline: 1.5857x; 1.0017x over previous
#include <cuda_runtime.h>

typedef unsigned long long u64;
#define DI __device__ __forceinline__

// Fixed average-trace buffer (length 120) from the reference module
__constant__ float c_avg[120] = {
 0.0256f,0.0823f,0.1157f,0.1315f,0.1366f,0.1369f,0.1347f,0.1308f,0.1259f,0.1205f,
 0.1146f,0.1086f,0.1028f,0.0970f,0.0913f,0.0858f,0.0805f,0.0756f,0.0708f,0.0664f,
 0.0623f,0.0584f,0.0549f,0.0515f,0.0485f,0.0456f,0.0429f,0.0404f,0.0381f,0.0360f,
 0.0340f,0.0321f,0.0304f,0.0287f,0.0272f,0.0258f,0.0245f,0.0233f,0.0222f,0.0211f,
 0.0201f,0.0191f,0.0182f,0.0173f,0.0165f,0.0158f,0.0150f,0.0143f,0.0137f,0.0130f,
 0.0125f,0.0119f,0.0114f,0.0108f,0.0104f,0.0099f,0.0095f,0.0091f,0.0087f,0.0083f,
 0.0080f,0.0077f,0.0074f,0.0071f,0.0068f,0.0065f,0.0062f,0.0060f,0.0058f,0.0055f,
 0.0053f,0.0050f,0.0049f,0.0047f,0.0045f,0.0044f,0.0042f,0.0040f,0.0039f,0.0038f,
 0.0036f,0.0034f,0.0033f,0.0032f,0.0031f,0.0030f,0.0029f,0.0028f,0.0027f,0.0026f,
 0.0025f,0.0024f,0.0023f,0.0022f,0.0021f,0.0021f,0.0020f,0.0019f,0.0018f,0.0018f,
 0.0017f,0.0017f,0.0016f,0.0016f,0.0015f,0.0015f,0.0014f,0.0014f,0.0013f,0.0013f,
 0.0013f,0.0012f,0.0012f,0.0011f,0.0011f,0.0011f,0.0010f,0.0010f,0.0010f,0.0009f
};

DI u64 pk2(float lo, float hi){ u64 r; asm("mov.b64 %0, {%1,%2};" : "=l"(r) : "f"(lo), "f"(hi)); return r; }
DI void up2(u64 v, float& lo, float& hi){ asm("mov.b64 {%0,%1}, %2;" : "=f"(lo), "=f"(hi) : "l"(v)); }
DI u64 ffma2(u64 a, u64 b, u64 c){ u64 d; asm("fma.rn.f32x2 %0, %1, %2, %3;" : "=l"(d) : "l"(a), "l"(b), "l"(c)); return d; }
DI float hadd2(u64 v){ float lo, hi; up2(v, lo, hi); return lo + hi; }
// Single-MUFU tanh. sigmoid pre-halved: sig = 0.5 + 0.5*tanh(x/2), /2 folded into weights.
DI float tanhfast(float x){ float y; asm("tanh.approx.f32 %0, %1;" : "=f"(y) : "f"(x)); return y; }
DI float sig_h(float xh){ return fmaf(tanhfast(xh), 0.5f, 0.5f); }

// Shared memory layout (bytes). 128 seqs per block, thread-pair (2p,2p+1) handles
// seqs p and p+64; half=tid&1 selects even/odd units of BOTH sequences.
// i/f/o-gate rows PRE-SCALED by 0.5; g-gate unscaled.
#define OFF_WIF   0        // ulonglong2 wIF[30][15]   : 7200  ({i,f} k-pairs, x0.5)
#define OFF_WGO   7200     // ulonglong2 wGO[30][15]   : 7200  ({g,o}: g x1, o x0.5)
#define OFF_W13   14400    // float4 w13S[15][2]       : 480
#define OFF_W2    14880    // u64 w2S[4][15]           : 480
#define OFF_BASEA 15360    // float4 baseA[15][128]    : 30720 (seq p)
#define OFF_BASEB 46080    // float4 baseB[15][128]    : 30720 (seq p+64)
#define SMEM_BYTES 76800

__global__ __launch_bounds__(128, 2)
void lstm_trace_kernel(const float* __restrict__ features,
                       const float* __restrict__ w_ih1,
                       const float* __restrict__ w_hh1,
                       const float* __restrict__ b1,
                       const float* __restrict__ w_ih2,
                       const float* __restrict__ w_hh2,
                       const float* __restrict__ b2,
                       float* __restrict__ out)
{
    extern __shared__ char smraw[];
    ulonglong2* wIF   = (ulonglong2*)(smraw + OFF_WIF);
    ulonglong2* wGO   = (ulonglong2*)(smraw + OFF_WGO);
    float4*     w13S  = (float4*)    (smraw + OFF_W13);
    u64*        w2S   = (u64*)       (smraw + OFF_W2);
    float4*     baseA = (float4*)    (smraw + OFF_BASEA);
    float4*     baseB = (float4*)    (smraw + OFF_BASEB);

    const int tid  = threadIdx.x;
    const int half = tid & 1;                    // 0: even units, 1: odd units
    const int pair = tid >> 1;                   // 0..63
    const int seqA = blockIdx.x * 128 + pair;
    const int seqB = seqA + 64;

    // ---- stage recurrent weight tables (k-packed pairs, sigmoid gates x0.5) ----
    for (int e = tid; e < 450; e += 128){
        int r  = e / 15, k2 = e % 15;
        int u  = (r < 15) ? 2*r : 2*(r-15) + 1;
        int c0 = 2*k2, c1 = 2*k2 + 1;
        ulonglong2 a, b;
        a.x = pk2(0.5f*w_hh1[      u *30 + c0], 0.5f*w_hh1[      u *30 + c1]);  // i
        a.y = pk2(0.5f*w_hh1[(30 + u)*30 + c0], 0.5f*w_hh1[(30 + u)*30 + c1]);  // f
        b.x = pk2(      w_hh1[(60 + u)*30 + c0],      w_hh1[(60 + u)*30 + c1]); // g
        b.y = pk2(0.5f*w_hh1[(90 + u)*30 + c0], 0.5f*w_hh1[(90 + u)*30 + c1]);  // o
        wIF[e] = a; wGO[e] = b;
    }
    if (tid < 30){
        int j = tid >> 1, hh = tid & 1, u = 2*j + hh;
        float4 v;
        v.x = 0.5f*w_ih1[      u *13 + 12];
        v.y = 0.5f*w_ih1[(30 + u)*13 + 12];
        v.z =       w_ih1[(60 + u)*13 + 12];
        v.w = 0.5f*w_ih1[(90 + u)*13 + 12];
        w13S[j*2 + hh] = v;
    }
    if (tid < 60){
        int g = tid / 15, k2 = tid % 15;
        float s = (g == 2) ? 1.0f : 0.5f;
        w2S[tid] = pk2(s*w_ih2[g*30 + 2*k2], s*w_ih2[g*30 + 2*k2 + 1]);
    }

    // ---- per-thread time-invariant bases (own 15 units x 4 gates, both seqs) ----
    #pragma unroll
    for (int sb = 0; sb < 2; sb++){
        int seq = sb ? seqB : seqA;
        float4* baseS = sb ? baseB : baseA;
        float f[12];
        const float4* fp = reinterpret_cast<const float4*>(features) + (size_t)seq * 3;
        float4 fa = fp[0], fb = fp[1], fc = fp[2];
        f[0]=fa.x; f[1]=fa.y; f[2]=fa.z; f[3]=fa.w;
        f[4]=fb.x; f[5]=fb.y; f[6]=fb.z; f[7]=fb.w;
        f[8]=fc.x; f[9]=fc.y; f[10]=fc.z; f[11]=fc.w;
        #pragma unroll 1
        for (int j = 0; j < 15; j++){
            int u = 2*j + half;
            float4 bs;
            float* bsv = &bs.x;
            #pragma unroll
            for (int g = 0; g < 4; g++){
                int row = g*30 + u;
                float s = __ldg(&b1[row]);
                #pragma unroll
                for (int ff = 0; ff < 12; ff++)
                    s = fmaf(__ldg(&w_ih1[row*13 + ff]), f[ff], s);
                bsv[g] = (g == 2) ? s : 0.5f*s;
            }
            baseS[j*128 + tid] = bs;
        }
    }
    __syncthreads();

    // ---- per-thread recurrent state (two sequences) ----
    u64   hpkA[15], hpkB[15];     // (h[2j], h[2j+1]) full layer-1 h per seq
    float c1A[15],  c1B[15];      // cell state for OWN 15 units per seq
    #pragma unroll
    for (int j = 0; j < 15; j++){
        hpkA[j] = 0ull; hpkB[j] = 0ull; c1A[j] = 0.0f; c1B[j] = 0.0f;
    }
    // layer-2 state: each thread of the pair owns ONE sequence's layer 2
    float h2 = 0.0f, c2 = 0.0f;
    const float b2r0 = 0.5f*b2[0], b2r1 = 0.5f*b2[1], b2r2 = b2[2], b2r3 = 0.5f*b2[3];
    const float wh20 = 0.5f*w_hh2[0], wh21 = 0.5f*w_hh2[1], wh22 = w_hh2[2], wh23 = 0.5f*w_hh2[3];
    float* myOut = out + (size_t)(half ? seqB : seqA) * 120;

    const ulonglong2* myWIF  = wIF + (half*15) * 15;
    const ulonglong2* myWGO  = wGO + (half*15) * 15;
    const float4*     myBA   = baseA + tid;
    const float4*     myBB   = baseB + tid;
    const float4*     myW13  = w13S + half;

    // ---- time recurrence ----
    #pragma unroll 1
    for (int t = 0; t < 120; t++){
        const float av = c_avg[t];
        float nhA[15], nhB[15];

        // unroll 2: bounded live accumulator set (16 u64) + LDS prefetch window
        #pragma unroll 2
        for (int j = 0; j < 15; j++){
            const ulonglong2* wif = myWIF + j*15;
            const ulonglong2* wgo = myWGO + j*15;
            float4 bsA = myBA[j*128];
            float4 bsB = myBB[j*128];
            float4 w13 = myW13[j*2];
            float wx = w13.x*av, wy = w13.y*av, wz = w13.z*av, ww = w13.w*av;
            u64 aiA = pk2(bsA.x, wx), afA = pk2(bsA.y, wy);
            u64 agA = pk2(bsA.z, wz), aoA = pk2(bsA.w, ww);
            u64 aiB = pk2(bsB.x, wx), afB = pk2(bsB.y, wy);
            u64 agB = pk2(bsB.z, wz), aoB = pk2(bsB.w, ww);
            #pragma unroll
            for (int k2 = 0; k2 < 15; k2++){
                ulonglong2 a = wif[k2], b = wgo[k2];
                u64 hA = hpkA[k2], hB = hpkB[k2];
                aiA = ffma2(a.x, hA, aiA); afA = ffma2(a.y, hA, afA);
                agA = ffma2(b.x, hA, agA); aoA = ffma2(b.y, hA, aoA);
                aiB = ffma2(a.x, hB, aiB); afB = ffma2(a.y, hB, afB);
                agB = ffma2(b.x, hB, agB); aoB = ffma2(b.y, hB, aoB);
            }
            {
                float si = sig_h(hadd2(aiA));
                float sf = sig_h(hadd2(afA));
                float tg = tanhfast(hadd2(agA));
                float so = sig_h(hadd2(aoA));
                float cc = fmaf(sf, c1A[j], si*tg);
                c1A[j] = cc;
                nhA[j] = so * tanhfast(cc);
            }
            {
                float si = sig_h(hadd2(aiB));
                float sf = sig_h(hadd2(afB));
                float tg = tanhfast(hadd2(agB));
                float so = sig_h(hadd2(aoB));
                float cc = fmaf(sf, c1B[j], si*tg);
                c1B[j] = cc;
                nhB[j] = so * tanhfast(cc);
            }
        }

        // exchange new h with partner thread, repack as (even, odd) pairs
        #pragma unroll
        for (int j = 0; j < 15; j++){
            float oA = __shfl_xor_sync(0xFFFFFFFFu, nhA[j], 1);
            float oB = __shfl_xor_sync(0xFFFFFFFFu, nhB[j], 1);
            hpkA[j] = half ? pk2(oA, nhA[j]) : pk2(nhA[j], oA);
            hpkB[j] = half ? pk2(oB, nhB[j]) : pk2(nhB[j], oB);
        }

        // layer 2: this thread handles ONE sequence (half==0 -> A, half==1 -> B)
        u64 a0 = pk2(b2r0, wh20*h2);
        u64 a1 = pk2(b2r1, wh21*h2);
        u64 a2 = pk2(b2r2, wh22*h2);
        u64 a3 = pk2(b2r3, wh23*h2);
        #pragma unroll
        for (int k2 = 0; k2 < 15; k2++){
            u64 h = half ? hpkB[k2] : hpkA[k2];
            a0 = ffma2(w2S[k2],      h, a0);
            a1 = ffma2(w2S[15 + k2], h, a1);
            a2 = ffma2(w2S[30 + k2], h, a2);
            a3 = ffma2(w2S[45 + k2], h, a3);
        }
        float si2 = sig_h(hadd2(a0));
        float sf2 = sig_h(hadd2(a1));
        float tg2 = tanhfast(hadd2(a2));
        float so2 = sig_h(hadd2(a3));
        c2 = fmaf(sf2, c2, si2*tg2);
        h2 = so2 * tanhfast(c2);

        myOut[t] = h2;
    }
}

extern "C" void kernel_launch(void* const* d_in, const int* in_sizes, int n_in,
                              void* d_out, int out_size)
{
    const float* features = (const float*)d_in[0];
    const float* w_ih1    = (const float*)d_in[1];
    const float* w_hh1    = (const float*)d_in[2];
    const float* b1       = (const float*)d_in[3];
    const float* w_ih2    = (const float*)d_in[4];
    const float* w_hh2    = (const float*)d_in[5];
    const float* b2       = (const float*)d_in[6];
    float* out = (float*)d_out;

    cudaFuncSetAttribute(lstm_trace_kernel,
                         cudaFuncAttributeMaxDynamicSharedMemorySize, SMEM_BYTES);
    lstm_trace_kernel<<<256, 128, SMEM_BYTES>>>(features, w_ih1, w_hh1, b1,
                                                w_ih2, w_hh2, b2, out);
}

// round 12
// speedup vs baseline: 1.5966x; 1.0069x over previous
#include <cuda_runtime.h>

typedef unsigned long long u64;
#define DI __device__ __forceinline__

// Fixed average-trace buffer (length 120) from the reference module
__constant__ float c_avg[120] = {
 0.0256f,0.0823f,0.1157f,0.1315f,0.1366f,0.1369f,0.1347f,0.1308f,0.1259f,0.1205f,
 0.1146f,0.1086f,0.1028f,0.0970f,0.0913f,0.0858f,0.0805f,0.0756f,0.0708f,0.0664f,
 0.0623f,0.0584f,0.0549f,0.0515f,0.0485f,0.0456f,0.0429f,0.0404f,0.0381f,0.0360f,
 0.0340f,0.0321f,0.0304f,0.0287f,0.0272f,0.0258f,0.0245f,0.0233f,0.0222f,0.0211f,
 0.0201f,0.0191f,0.0182f,0.0173f,0.0165f,0.0158f,0.0150f,0.0143f,0.0137f,0.0130f,
 0.0125f,0.0119f,0.0114f,0.0108f,0.0104f,0.0099f,0.0095f,0.0091f,0.0087f,0.0083f,
 0.0080f,0.0077f,0.0074f,0.0071f,0.0068f,0.0065f,0.0062f,0.0060f,0.0058f,0.0055f,
 0.0053f,0.0050f,0.0049f,0.0047f,0.0045f,0.0044f,0.0042f,0.0040f,0.0039f,0.0038f,
 0.0036f,0.0034f,0.0033f,0.0032f,0.0031f,0.0030f,0.0029f,0.0028f,0.0027f,0.0026f,
 0.0025f,0.0024f,0.0023f,0.0022f,0.0021f,0.0021f,0.0020f,0.0019f,0.0018f,0.0018f,
 0.0017f,0.0017f,0.0016f,0.0016f,0.0015f,0.0015f,0.0014f,0.0014f,0.0013f,0.0013f,
 0.0013f,0.0012f,0.0012f,0.0011f,0.0011f,0.0011f,0.0010f,0.0010f,0.0010f,0.0009f
};

DI u64 pk2(float lo, float hi){ u64 r; asm("mov.b64 %0, {%1,%2};" : "=l"(r) : "f"(lo), "f"(hi)); return r; }
DI void up2(u64 v, float& lo, float& hi){ asm("mov.b64 {%0,%1}, %2;" : "=f"(lo), "=f"(hi) : "l"(v)); }
DI u64 ffma2(u64 a, u64 b, u64 c){ u64 d; asm("fma.rn.f32x2 %0, %1, %2, %3;" : "=l"(d) : "l"(a), "l"(b), "l"(c)); return d; }
DI float hadd2(u64 v){ float lo, hi; up2(v, lo, hi); return lo + hi; }
// Single-MUFU tanh. sigmoid pre-halved: sig = 0.5 + 0.5*tanh(x/2), /2 folded into weights.
DI float tanhfast(float x){ float y; asm("tanh.approx.f32 %0, %1;" : "=f"(y) : "f"(x)); return y; }
DI float sig_h(float xh){ return fmaf(tanhfast(xh), 0.5f, 0.5f); }

// Shared memory layout (bytes). Up to 128 seqs per block; thread-pair (2p,2p+1)
// handles seqs (base+p, base+halfc+p); half=tid&1 selects even/odd units.
// i/f/o-gate rows PRE-SCALED by 0.5; g-gate unscaled.
#define OFF_WIF   0        // ulonglong2 wIF[30][15]   : 7200  ({i,f} k-pairs, x0.5)
#define OFF_WGO   7200     // ulonglong2 wGO[30][15]   : 7200  ({g,o}: g x1, o x0.5)
#define OFF_W13   14400    // float4 w13S[15][2]       : 480
#define OFF_W2    14880    // u64 w2S[4][15]           : 480
#define OFF_BASEA 15360    // float4 baseA[15][128]    : 30720 (seq A)
#define OFF_BASEB 46080    // float4 baseB[15][128]    : 30720 (seq B)
#define SMEM_BYTES 76800

// Balanced decomposition: 296 CTAs (= 148 SMs x 2), first 208 take 111 seqs, rest 110.
#define NCTA   296
#define NBIG   208
#define NSEQS  32768

__global__ __launch_bounds__(128, 2)
void lstm_trace_kernel(const float* __restrict__ features,
                       const float* __restrict__ w_ih1,
                       const float* __restrict__ w_hh1,
                       const float* __restrict__ b1,
                       const float* __restrict__ w_ih2,
                       const float* __restrict__ w_hh2,
                       const float* __restrict__ b2,
                       float* __restrict__ out)
{
    extern __shared__ char smraw[];
    ulonglong2* wIF   = (ulonglong2*)(smraw + OFF_WIF);
    ulonglong2* wGO   = (ulonglong2*)(smraw + OFF_WGO);
    float4*     w13S  = (float4*)    (smraw + OFF_W13);
    u64*        w2S   = (u64*)       (smraw + OFF_W2);
    float4*     baseA = (float4*)    (smraw + OFF_BASEA);
    float4*     baseB = (float4*)    (smraw + OFF_BASEB);

    const int tid  = threadIdx.x;
    const int half = tid & 1;                    // 0: even units, 1: odd units
    const int pair = tid >> 1;                   // 0..63
    const int bid  = blockIdx.x;

    // Balanced seq range for this CTA
    const int cnt   = (bid < NBIG) ? 111 : 110;
    const int base  = bid * 110 + (bid < NBIG ? bid : NBIG);
    const int halfc = (cnt + 1) >> 1;            // 56 or 55
    const bool vA   = (pair < halfc);
    const bool vB   = (halfc + pair) < cnt;
    const int seqA  = vA ? (base + pair)         : 0;
    const int seqB  = vB ? (base + halfc + pair) : 0;

    // ---- stage recurrent weight tables (k-packed pairs, sigmoid gates x0.5) ----
    for (int e = tid; e < 450; e += 128){
        int r  = e / 15, k2 = e % 15;
        int u  = (r < 15) ? 2*r : 2*(r-15) + 1;
        int c0 = 2*k2, c1 = 2*k2 + 1;
        ulonglong2 a, b;
        a.x = pk2(0.5f*w_hh1[      u *30 + c0], 0.5f*w_hh1[      u *30 + c1]);  // i
        a.y = pk2(0.5f*w_hh1[(30 + u)*30 + c0], 0.5f*w_hh1[(30 + u)*30 + c1]);  // f
        b.x = pk2(      w_hh1[(60 + u)*30 + c0],      w_hh1[(60 + u)*30 + c1]); // g
        b.y = pk2(0.5f*w_hh1[(90 + u)*30 + c0], 0.5f*w_hh1[(90 + u)*30 + c1]);  // o
        wIF[e] = a; wGO[e] = b;
    }
    if (tid < 30){
        int j = tid >> 1, hh = tid & 1, u = 2*j + hh;
        float4 v;
        v.x = 0.5f*w_ih1[      u *13 + 12];
        v.y = 0.5f*w_ih1[(30 + u)*13 + 12];
        v.z =       w_ih1[(60 + u)*13 + 12];
        v.w = 0.5f*w_ih1[(90 + u)*13 + 12];
        w13S[j*2 + hh] = v;
    }
    if (tid < 60){
        int g = tid / 15, k2 = tid % 15;
        float s = (g == 2) ? 1.0f : 0.5f;
        w2S[tid] = pk2(s*w_ih2[g*30 + 2*k2], s*w_ih2[g*30 + 2*k2 + 1]);
    }

    // ---- per-thread time-invariant bases (own 15 units x 4 gates, both seqs) ----
    #pragma unroll
    for (int sb = 0; sb < 2; sb++){
        int seq = sb ? seqB : seqA;
        float4* baseS = sb ? baseB : baseA;
        float f[12];
        const float4* fp = reinterpret_cast<const float4*>(features) + (size_t)seq * 3;
        float4 fa = fp[0], fb = fp[1], fc = fp[2];
        f[0]=fa.x; f[1]=fa.y; f[2]=fa.z; f[3]=fa.w;
        f[4]=fb.x; f[5]=fb.y; f[6]=fb.z; f[7]=fb.w;
        f[8]=fc.x; f[9]=fc.y; f[10]=fc.z; f[11]=fc.w;
        #pragma unroll 1
        for (int j = 0; j < 15; j++){
            int u = 2*j + half;
            float4 bs;
            float* bsv = &bs.x;
            #pragma unroll
            for (int g = 0; g < 4; g++){
                int row = g*30 + u;
                float s = __ldg(&b1[row]);
                #pragma unroll
                for (int ff = 0; ff < 12; ff++)
                    s = fmaf(__ldg(&w_ih1[row*13 + ff]), f[ff], s);
                bsv[g] = (g == 2) ? s : 0.5f*s;
            }
            baseS[j*128 + tid] = bs;
        }
    }
    __syncthreads();

    // ---- per-thread recurrent state (two sequences) ----
    u64   hpkA[15], hpkB[15];     // (h[2j], h[2j+1]) full layer-1 h per seq
    float c1A[15],  c1B[15];      // cell state for OWN 15 units per seq
    #pragma unroll
    for (int j = 0; j < 15; j++){
        hpkA[j] = 0ull; hpkB[j] = 0ull; c1A[j] = 0.0f; c1B[j] = 0.0f;
    }
    // layer-2 state: each thread of the pair owns ONE sequence's layer 2
    float h2 = 0.0f, c2 = 0.0f;
    const float b2r0 = 0.5f*b2[0], b2r1 = 0.5f*b2[1], b2r2 = b2[2], b2r3 = 0.5f*b2[3];
    const float wh20 = 0.5f*w_hh2[0], wh21 = 0.5f*w_hh2[1], wh22 = w_hh2[2], wh23 = 0.5f*w_hh2[3];
    const bool  myValid = half ? vB : vA;
    float* myOut = out + (size_t)(half ? seqB : seqA) * 120;

    const ulonglong2* myWIF  = wIF + (half*15) * 15;
    const ulonglong2* myWGO  = wGO + (half*15) * 15;
    const float4*     myBA   = baseA + tid;
    const float4*     myBB   = baseB + tid;
    const float4*     myW13  = w13S + half;

    // ---- time recurrence ----
    #pragma unroll 1
    for (int t = 0; t < 120; t++){
        const float av = c_avg[t];
        float nhA[15], nhB[15];

        // unroll 2: bounded live accumulator set (16 u64) + LDS prefetch window
        #pragma unroll 2
        for (int j = 0; j < 15; j++){
            const ulonglong2* wif = myWIF + j*15;
            const ulonglong2* wgo = myWGO + j*15;
            float4 bsA = myBA[j*128];
            float4 bsB = myBB[j*128];
            float4 w13 = myW13[j*2];
            float wx = w13.x*av, wy = w13.y*av, wz = w13.z*av, ww = w13.w*av;
            u64 aiA = pk2(bsA.x, wx), afA = pk2(bsA.y, wy);
            u64 agA = pk2(bsA.z, wz), aoA = pk2(bsA.w, ww);
            u64 aiB = pk2(bsB.x, wx), afB = pk2(bsB.y, wy);
            u64 agB = pk2(bsB.z, wz), aoB = pk2(bsB.w, ww);
            #pragma unroll
            for (int k2 = 0; k2 < 15; k2++){
                ulonglong2 a = wif[k2], b = wgo[k2];
                u64 hA = hpkA[k2], hB = hpkB[k2];
                aiA = ffma2(a.x, hA, aiA); afA = ffma2(a.y, hA, afA);
                agA = ffma2(b.x, hA, agA); aoA = ffma2(b.y, hA, aoA);
                aiB = ffma2(a.x, hB, aiB); afB = ffma2(a.y, hB, afB);
                agB = ffma2(b.x, hB, agB); aoB = ffma2(b.y, hB, aoB);
            }
            {
                float si = sig_h(hadd2(aiA));
                float sf = sig_h(hadd2(afA));
                float tg = tanhfast(hadd2(agA));
                float so = sig_h(hadd2(aoA));
                float cc = fmaf(sf, c1A[j], si*tg);
                c1A[j] = cc;
                nhA[j] = so * tanhfast(cc);
            }
            {
                float si = sig_h(hadd2(aiB));
                float sf = sig_h(hadd2(afB));
                float tg = tanhfast(hadd2(agB));
                float so = sig_h(hadd2(aoB));
                float cc = fmaf(sf, c1B[j], si*tg);
                c1B[j] = cc;
                nhB[j] = so * tanhfast(cc);
            }
        }

        // exchange new h with partner thread, repack as (even, odd) pairs.
        // Partner lanes always share active/inactive state, so full-mask is safe.
        #pragma unroll
        for (int j = 0; j < 15; j++){
            float oA = __shfl_xor_sync(0xFFFFFFFFu, nhA[j], 1);
            float oB = __shfl_xor_sync(0xFFFFFFFFu, nhB[j], 1);
            hpkA[j] = half ? pk2(oA, nhA[j]) : pk2(nhA[j], oA);
            hpkB[j] = half ? pk2(oB, nhB[j]) : pk2(nhB[j], oB);
        }

        // layer 2: this thread handles ONE sequence (half==0 -> A, half==1 -> B)
        u64 a0 = pk2(b2r0, wh20*h2);
        u64 a1 = pk2(b2r1, wh21*h2);
        u64 a2 = pk2(b2r2, wh22*h2);
        u64 a3 = pk2(b2r3, wh23*h2);
        #pragma unroll
        for (int k2 = 0; k2 < 15; k2++){
            u64 h = half ? hpkB[k2] : hpkA[k2];
            a0 = ffma2(w2S[k2],      h, a0);
            a1 = ffma2(w2S[15 + k2], h, a1);
            a2 = ffma2(w2S[30 + k2], h, a2);
            a3 = ffma2(w2S[45 + k2], h, a3);
        }
        float si2 = sig_h(hadd2(a0));
        float sf2 = sig_h(hadd2(a1));
        float tg2 = tanhfast(hadd2(a2));
        float so2 = sig_h(hadd2(a3));
        c2 = fmaf(sf2, c2, si2*tg2);
        h2 = so2 * tanhfast(c2);

        if (myValid) myOut[t] = h2;
    }
}

extern "C" void kernel_launch(void* const* d_in, const int* in_sizes, int n_in,
                              void* d_out, int out_size)
{
    const float* features = (const float*)d_in[0];
    const float* w_ih1    = (const float*)d_in[1];
    const float* w_hh1    = (const float*)d_in[2];
    const float* b1       = (const float*)d_in[3];
    const float* w_ih2    = (const float*)d_in[4];
    const float* w_hh2    = (const float*)d_in[5];
    const float* b2       = (const float*)d_in[6];
    float* out = (float*)d_out;

    cudaFuncSetAttribute(lstm_trace_kernel,
                         cudaFuncAttributeMaxDynamicSharedMemorySize, SMEM_BYTES);
    lstm_trace_kernel<<<NCTA, 128, SMEM_BYTES>>>(features, w_ih1, w_hh1, b1,
                                                 w_ih2, w_hh2, b2, out);
}

// round 13
// speedup vs baseline: 1.6224x; 1.0162x over previous
#include <cuda_runtime.h>

typedef unsigned long long u64;
#define DI __device__ __forceinline__

// Fixed average-trace buffer (length 120) from the reference module
__constant__ float c_avg[120] = {
 0.0256f,0.0823f,0.1157f,0.1315f,0.1366f,0.1369f,0.1347f,0.1308f,0.1259f,0.1205f,
 0.1146f,0.1086f,0.1028f,0.0970f,0.0913f,0.0858f,0.0805f,0.0756f,0.0708f,0.0664f,
 0.0623f,0.0584f,0.0549f,0.0515f,0.0485f,0.0456f,0.0429f,0.0404f,0.0381f,0.0360f,
 0.0340f,0.0321f,0.0304f,0.0287f,0.0272f,0.0258f,0.0245f,0.0233f,0.0222f,0.0211f,
 0.0201f,0.0191f,0.0182f,0.0173f,0.0165f,0.0158f,0.0150f,0.0143f,0.0137f,0.0130f,
 0.0125f,0.0119f,0.0114f,0.0108f,0.0104f,0.0099f,0.0095f,0.0091f,0.0087f,0.0083f,
 0.0080f,0.0077f,0.0074f,0.0071f,0.0068f,0.0065f,0.0062f,0.0060f,0.0058f,0.0055f,
 0.0053f,0.0050f,0.0049f,0.0047f,0.0045f,0.0044f,0.0042f,0.0040f,0.0039f,0.0038f,
 0.0036f,0.0034f,0.0033f,0.0032f,0.0031f,0.0030f,0.0029f,0.0028f,0.0027f,0.0026f,
 0.0025f,0.0024f,0.0023f,0.0022f,0.0021f,0.0021f,0.0020f,0.0019f,0.0018f,0.0018f,
 0.0017f,0.0017f,0.0016f,0.0016f,0.0015f,0.0015f,0.0014f,0.0014f,0.0013f,0.0013f,
 0.0013f,0.0012f,0.0012f,0.0011f,0.0011f,0.0011f,0.0010f,0.0010f,0.0010f,0.0009f
};

DI u64 pk2(float lo, float hi){ u64 r; asm("mov.b64 %0, {%1,%2};" : "=l"(r) : "f"(lo), "f"(hi)); return r; }
DI void up2(u64 v, float& lo, float& hi){ asm("mov.b64 {%0,%1}, %2;" : "=f"(lo), "=f"(hi) : "l"(v)); }
DI u64 ffma2(u64 a, u64 b, u64 c){ u64 d; asm("fma.rn.f32x2 %0, %1, %2, %3;" : "=l"(d) : "l"(a), "l"(b), "l"(c)); return d; }
DI float hadd2(u64 v){ float lo, hi; up2(v, lo, hi); return lo + hi; }
// Single-MUFU tanh. sigmoid pre-halved: sig = 0.5 + 0.5*tanh(x/2), /2 folded into weights.
DI float tanhfast(float x){ float y; asm("tanh.approx.f32 %0, %1;" : "=f"(y) : "f"(x)); return y; }
DI float sig_h(float xh){ return fmaf(tanhfast(xh), 0.5f, 0.5f); }

// Shared memory layout (bytes). Thread-pair (2p,2p+1) handles seqs (base+p, base+halfc+p);
// half=tid&1 selects even/odd units. i/f/o-gate rows PRE-SCALED by 0.5; g unscaled.
#define OFF_WIF   0        // ulonglong2 wIF[30][15]   : 7200
#define OFF_WGO   7200     // ulonglong2 wGO[30][15]   : 7200
#define OFF_W13   14400    // float4 w13S[15][2]       : 480
#define OFF_W2    14880    // u64 w2S[4][15]           : 480
#define OFF_BASEA 15360    // float4 baseA[15][128]    : 30720 (seq A)
#define OFF_BASEB 46080    // float4 baseB[15][128]    : 30720 (seq B)
#define SMEM_BYTES 76800

// 296 CTAs (= 148 SMs x 2); first 208 take 111 seqs, rest 110.
#define NCTA   296
#define NBIG   208

__global__ __launch_bounds__(128, 2)
void lstm_trace_kernel(const float* __restrict__ features,
                       const float* __restrict__ w_ih1,
                       const float* __restrict__ w_hh1,
                       const float* __restrict__ b1,
                       const float* __restrict__ w_ih2,
                       const float* __restrict__ w_hh2,
                       const float* __restrict__ b2,
                       float* __restrict__ out)
{
    extern __shared__ char smraw[];
    ulonglong2* wIF   = (ulonglong2*)(smraw + OFF_WIF);
    ulonglong2* wGO   = (ulonglong2*)(smraw + OFF_WGO);
    float4*     w13S  = (float4*)    (smraw + OFF_W13);
    u64*        w2S   = (u64*)       (smraw + OFF_W2);
    float4*     baseA = (float4*)    (smraw + OFF_BASEA);
    float4*     baseB = (float4*)    (smraw + OFF_BASEB);

    const int tid  = threadIdx.x;
    const int half = tid & 1;
    const int pair = tid >> 1;
    const int bid  = blockIdx.x;

    const int cnt   = (bid < NBIG) ? 111 : 110;
    const int base  = bid * 110 + (bid < NBIG ? bid : NBIG);
    const int halfc = (cnt + 1) >> 1;
    const bool vA   = (pair < halfc);
    const bool vB   = (halfc + pair) < cnt;
    const int seqA  = vA ? (base + pair)         : 0;
    const int seqB  = vB ? (base + halfc + pair) : 0;

    // ---- stage recurrent weight tables (k-packed pairs, sigmoid gates x0.5) ----
    for (int e = tid; e < 450; e += 128){
        int r  = e / 15, k2 = e % 15;
        int u  = (r < 15) ? 2*r : 2*(r-15) + 1;
        int c0 = 2*k2, c1 = 2*k2 + 1;
        ulonglong2 a, b;
        a.x = pk2(0.5f*w_hh1[      u *30 + c0], 0.5f*w_hh1[      u *30 + c1]);  // i
        a.y = pk2(0.5f*w_hh1[(30 + u)*30 + c0], 0.5f*w_hh1[(30 + u)*30 + c1]);  // f
        b.x = pk2(      w_hh1[(60 + u)*30 + c0],      w_hh1[(60 + u)*30 + c1]); // g
        b.y = pk2(0.5f*w_hh1[(90 + u)*30 + c0], 0.5f*w_hh1[(90 + u)*30 + c1]);  // o
        wIF[e] = a; wGO[e] = b;
    }
    if (tid < 30){
        int j = tid >> 1, hh = tid & 1, u = 2*j + hh;
        float4 v;
        v.x = 0.5f*w_ih1[      u *13 + 12];
        v.y = 0.5f*w_ih1[(30 + u)*13 + 12];
        v.z =       w_ih1[(60 + u)*13 + 12];
        v.w = 0.5f*w_ih1[(90 + u)*13 + 12];
        w13S[j*2 + hh] = v;
    }
    if (tid < 60){
        int g = tid / 15, k2 = tid % 15;
        float s = (g == 2) ? 1.0f : 0.5f;
        w2S[tid] = pk2(s*w_ih2[g*30 + 2*k2], s*w_ih2[g*30 + 2*k2 + 1]);
    }

    // ---- per-thread time-invariant bases ----
    #pragma unroll
    for (int sb = 0; sb < 2; sb++){
        int seq = sb ? seqB : seqA;
        float4* baseS = sb ? baseB : baseA;
        float f[12];
        const float4* fp = reinterpret_cast<const float4*>(features) + (size_t)seq * 3;
        float4 fa = fp[0], fb = fp[1], fc = fp[2];
        f[0]=fa.x; f[1]=fa.y; f[2]=fa.z; f[3]=fa.w;
        f[4]=fb.x; f[5]=fb.y; f[6]=fb.z; f[7]=fb.w;
        f[8]=fc.x; f[9]=fc.y; f[10]=fc.z; f[11]=fc.w;
        #pragma unroll 1
        for (int j = 0; j < 15; j++){
            int u = 2*j + half;
            float4 bs;
            float* bsv = &bs.x;
            #pragma unroll
            for (int g = 0; g < 4; g++){
                int row = g*30 + u;
                float s = __ldg(&b1[row]);
                #pragma unroll
                for (int ff = 0; ff < 12; ff++)
                    s = fmaf(__ldg(&w_ih1[row*13 + ff]), f[ff], s);
                bsv[g] = (g == 2) ? s : 0.5f*s;
            }
            baseS[j*128 + tid] = bs;
        }
    }
    __syncthreads();

    // ---- per-thread recurrent state (two sequences) ----
    u64   hpkA[15], hpkB[15];
    float c1A[15],  c1B[15];
    #pragma unroll
    for (int j = 0; j < 15; j++){
        hpkA[j] = 0ull; hpkB[j] = 0ull; c1A[j] = 0.0f; c1B[j] = 0.0f;
    }
    float h2 = 0.0f, c2 = 0.0f;
    const float b2r0 = 0.5f*b2[0], b2r1 = 0.5f*b2[1], b2r2 = b2[2], b2r3 = 0.5f*b2[3];
    const float wh20 = 0.5f*w_hh2[0], wh21 = 0.5f*w_hh2[1], wh22 = w_hh2[2], wh23 = 0.5f*w_hh2[3];
    const bool  myValid = half ? vB : vA;
    float* myOut = out + (size_t)(half ? seqB : seqA) * 120;

    const ulonglong2* myWIF  = wIF + (half*15) * 15;
    const ulonglong2* myWGO  = wGO + (half*15) * 15;
    const float4*     myBA   = baseA + tid;
    const float4*     myBB   = baseB + tid;
    const float4*     myW13  = w13S + half;

    // ---- time recurrence ----
    // Layer-2 for step t-1 is computed INSIDE iteration t, interleaved with the
    // j-loop matvec (both read only hpk = h(t-1)), hiding its MUFU chain.
    #pragma unroll 1
    for (int t = 0; t < 120; t++){
        const float av = c_avg[t];
        float nhA[15], nhB[15];

        // deferred layer 2 for the PREVIOUS step (t-1); reads hpk (= h(t-1))
        if (t > 0){
            u64 a0 = pk2(b2r0, wh20*h2);
            u64 a1 = pk2(b2r1, wh21*h2);
            u64 a2 = pk2(b2r2, wh22*h2);
            u64 a3 = pk2(b2r3, wh23*h2);
            #pragma unroll
            for (int k2 = 0; k2 < 15; k2++){
                u64 h = half ? hpkB[k2] : hpkA[k2];
                a0 = ffma2(w2S[k2],      h, a0);
                a1 = ffma2(w2S[15 + k2], h, a1);
                a2 = ffma2(w2S[30 + k2], h, a2);
                a3 = ffma2(w2S[45 + k2], h, a3);
            }
            float si2 = sig_h(hadd2(a0));
            float sf2 = sig_h(hadd2(a1));
            float tg2 = tanhfast(hadd2(a2));
            float so2 = sig_h(hadd2(a3));
            c2 = fmaf(sf2, c2, si2*tg2);
            h2 = so2 * tanhfast(c2);
            if (myValid) myOut[t-1] = h2;
        }

        // matvec + cell update; unroll 3 -> 24 independent FFMA2 chains in flight
        #pragma unroll 3
        for (int j = 0; j < 15; j++){
            const ulonglong2* wif = myWIF + j*15;
            const ulonglong2* wgo = myWGO + j*15;
            float4 bsA = myBA[j*128];
            float4 bsB = myBB[j*128];
            float4 w13 = myW13[j*2];
            float wx = w13.x*av, wy = w13.y*av, wz = w13.z*av, ww = w13.w*av;
            u64 aiA = pk2(bsA.x, wx), afA = pk2(bsA.y, wy);
            u64 agA = pk2(bsA.z, wz), aoA = pk2(bsA.w, ww);
            u64 aiB = pk2(bsB.x, wx), afB = pk2(bsB.y, wy);
            u64 agB = pk2(bsB.z, wz), aoB = pk2(bsB.w, ww);
            #pragma unroll
            for (int k2 = 0; k2 < 15; k2++){
                ulonglong2 a = wif[k2], b = wgo[k2];
                u64 hA = hpkA[k2], hB = hpkB[k2];
                aiA = ffma2(a.x, hA, aiA); afA = ffma2(a.y, hA, afA);
                agA = ffma2(b.x, hA, agA); aoA = ffma2(b.y, hA, aoA);
                aiB = ffma2(a.x, hB, aiB); afB = ffma2(a.y, hB, afB);
                agB = ffma2(b.x, hB, agB); aoB = ffma2(b.y, hB, aoB);
            }
            {
                float si = sig_h(hadd2(aiA));
                float sf = sig_h(hadd2(afA));
                float tg = tanhfast(hadd2(agA));
                float so = sig_h(hadd2(aoA));
                float cc = fmaf(sf, c1A[j], si*tg);
                c1A[j] = cc;
                nhA[j] = so * tanhfast(cc);
            }
            {
                float si = sig_h(hadd2(aiB));
                float sf = sig_h(hadd2(afB));
                float tg = tanhfast(hadd2(agB));
                float so = sig_h(hadd2(aoB));
                float cc = fmaf(sf, c1B[j], si*tg);
                c1B[j] = cc;
                nhB[j] = so * tanhfast(cc);
            }
        }

        // exchange new h with partner thread, repack as (even, odd) pairs
        #pragma unroll
        for (int j = 0; j < 15; j++){
            float oA = __shfl_xor_sync(0xFFFFFFFFu, nhA[j], 1);
            float oB = __shfl_xor_sync(0xFFFFFFFFu, nhB[j], 1);
            hpkA[j] = half ? pk2(oA, nhA[j]) : pk2(nhA[j], oA);
            hpkB[j] = half ? pk2(oB, nhB[j]) : pk2(nhB[j], oB);
        }
    }

    // final deferred layer 2 (t = 119)
    {
        u64 a0 = pk2(b2r0, wh20*h2);
        u64 a1 = pk2(b2r1, wh21*h2);
        u64 a2 = pk2(b2r2, wh22*h2);
        u64 a3 = pk2(b2r3, wh23*h2);
        #pragma unroll
        for (int k2 = 0; k2 < 15; k2++){
            u64 h = half ? hpkB[k2] : hpkA[k2];
            a0 = ffma2(w2S[k2],      h, a0);
            a1 = ffma2(w2S[15 + k2], h, a1);
            a2 = ffma2(w2S[30 + k2], h, a2);
            a3 = ffma2(w2S[45 + k2], h, a3);
        }
        float si2 = sig_h(hadd2(a0));
        float sf2 = sig_h(hadd2(a1));
        float tg2 = tanhfast(hadd2(a2));
        float so2 = sig_h(hadd2(a3));
        c2 = fmaf(sf2, c2, si2*tg2);
        h2 = so2 * tanhfast(c2);
        if (myValid) myOut[119] = h2;
    }
}

extern "C" void kernel_launch(void* const* d_in, const int* in_sizes, int n_in,
                              void* d_out, int out_size)
{
    const float* features = (const float*)d_in[0];
    const float* w_ih1    = (const float*)d_in[1];
    const float* w_hh1    = (const float*)d_in[2];
    const float* b1       = (const float*)d_in[3];
    const float* w_ih2    = (const float*)d_in[4];
    const float* w_hh2    = (const float*)d_in[5];
    const float* b2       = (const float*)d_in[6];
    float* out = (float*)d_out;

    cudaFuncSetAttribute(lstm_trace_kernel,
                         cudaFuncAttributeMaxDynamicSharedMemorySize, SMEM_BYTES);
    lstm_trace_kernel<<<NCTA, 128, SMEM_BYTES>>>(features, w_ih1, w_hh1, b1,
                                                 w_ih2, w_hh2, b2, out);
}

// round 15
// speedup vs baseline: 2.1246x; 1.3095x over previous
#include <cuda_runtime.h>
#include <cuda_fp16.h>
#include <cstdint>

#define DI __device__ __forceinline__

// Fixed average-trace buffer (length 120) from the reference module
__constant__ float c_avg[120] = {
 0.0256f,0.0823f,0.1157f,0.1315f,0.1366f,0.1369f,0.1347f,0.1308f,0.1259f,0.1205f,
 0.1146f,0.1086f,0.1028f,0.0970f,0.0913f,0.0858f,0.0805f,0.0756f,0.0708f,0.0664f,
 0.0623f,0.0584f,0.0549f,0.0515f,0.0485f,0.0456f,0.0429f,0.0404f,0.0381f,0.0360f,
 0.0340f,0.0321f,0.0304f,0.0287f,0.0272f,0.0258f,0.0245f,0.0233f,0.0222f,0.0211f,
 0.0201f,0.0191f,0.0182f,0.0173f,0.0165f,0.0158f,0.0150f,0.0143f,0.0137f,0.0130f,
 0.0125f,0.0119f,0.0114f,0.0108f,0.0104f,0.0099f,0.0095f,0.0091f,0.0087f,0.0083f,
 0.0080f,0.0077f,0.0074f,0.0071f,0.0068f,0.0065f,0.0062f,0.0060f,0.0058f,0.0055f,
 0.0053f,0.0050f,0.0049f,0.0047f,0.0045f,0.0044f,0.0042f,0.0040f,0.0039f,0.0038f,
 0.0036f,0.0034f,0.0033f,0.0032f,0.0031f,0.0030f,0.0029f,0.0028f,0.0027f,0.0026f,
 0.0025f,0.0024f,0.0023f,0.0022f,0.0021f,0.0021f,0.0020f,0.0019f,0.0018f,0.0018f,
 0.0017f,0.0017f,0.0016f,0.0016f,0.0015f,0.0015f,0.0014f,0.0014f,0.0013f,0.0013f,
 0.0013f,0.0012f,0.0012f,0.0011f,0.0011f,0.0011f,0.0010f,0.0010f,0.0010f,0.0009f
};

DI float tanhfast(float x){ float y; asm("tanh.approx.f32 %0, %1;" : "=f"(y) : "f"(x)); return y; }
DI float sig_h(float xh){ return fmaf(tanhfast(xh), 0.5f, 0.5f); }   // arg pre-halved
DI uint32_t f2h2(float lo, float hi){
    __half2 h = __floats2half2_rn(lo, hi);   // lo -> low half (first element)
    return *reinterpret_cast<uint32_t*>(&h);
}
DI uint32_t sm32(const void* p){ return (uint32_t)__cvta_generic_to_shared(p); }

// ---- SMEM layout (bytes) ----
// baseS: f32[128 seq][124] (stride 496B), gate order n = 4u+g, prescaled (i,f,o x0.5)
// w2S:   float4[30] layer-2 weights per unit, prescaled
// Ast:   per-warp A staging: 32 rows x 72 fp16 (144B padded stride)
#define BASE_STRIDE 124
#define OFF_BASE 0
#define OFF_W2   63488
#define OFF_AST  64000
#define SMEM_BYTES (64000 + 4*32*144)    // 82432

__global__ __launch_bounds__(128)
void lstm_mma_kernel(const float* __restrict__ features,
                     const float* __restrict__ w_ih1,
                     const float* __restrict__ w_hh1,
                     const float* __restrict__ b1,
                     const float* __restrict__ w_ih2,
                     const float* __restrict__ w_hh2,
                     const float* __restrict__ b2,
                     float* __restrict__ out)
{
    extern __shared__ char smraw[];
    float*  baseS = (float*)(smraw + OFF_BASE);
    float4* w2S   = (float4*)(smraw + OFF_W2);
    char*   Ast   = smraw + OFF_AST;

    const int tid  = threadIdx.x;
    const int wid  = tid >> 5, lane = tid & 31;
    const int g    = lane >> 2, tg = lane & 3;
    const int p    = tg >> 1;          // unit parity this lane handles post-exchange
    const int rsel = tg & 1;           // 0 -> row g, 1 -> row g+8
    const int rowA = g + 8*rsel;

    // ---- per-seq time-invariant base (prescaled), one seq per thread ----
    {
        const int seq = blockIdx.x*128 + tid;
        const float4* fp = (const float4*)features + (size_t)seq*3;
        float4 fa=fp[0], fb=fp[1], fc=fp[2];
        float f[12] = {fa.x,fa.y,fa.z,fa.w, fb.x,fb.y,fb.z,fb.w, fc.x,fc.y,fc.z,fc.w};
        float* dst = baseS + tid*BASE_STRIDE;
        #pragma unroll 1
        for (int u=0; u<30; u++){
            float4 bs; float* bv = &bs.x;
            #pragma unroll
            for (int gg=0; gg<4; gg++){
                int row = gg*30 + u;
                float s = __ldg(&b1[row]);
                #pragma unroll
                for (int ff=0; ff<12; ff++) s = fmaf(__ldg(&w_ih1[row*13+ff]), f[ff], s);
                bv[gg] = (gg==2) ? s : 0.5f*s;
            }
            *(float4*)(dst + u*4) = bs;
        }
    }
    if (tid < 30)
        w2S[tid] = make_float4(0.5f*w_ih2[tid], 0.5f*w_ih2[30+tid],
                               w_ih2[60+tid],   0.5f*w_ih2[90+tid]);
    __syncthreads();

    // ---- B fragments in registers (fp16, prescaled), loop-invariant ----
    // k-blocks: ks0 rows: src = even units (+ w13_hi at kk=15)
    //           ks1 rows: src = odd units (+ w13_lo at kk=15)
    // kstep 2,3 reuse ks0, ks1 (they multiply h_lo / av_lo).
    uint32_t Bf[2][15][2];
    #pragma unroll
    for (int ks=0; ks<2; ks++){
        #pragma unroll
        for (int nf=0; nf<15; nf++){
            int n = nf*8 + g, u = n>>2, g4 = n&3;
            float s = (g4==2) ? 1.0f : 0.5f;
            int prow = g4*30 + u;
            float v[4];
            #pragma unroll
            for (int q=0; q<4; q++){
                int kk = tg*2 + (q&1) + (q>>1)*8;
                float val;
                if (kk < 15) val = s*__ldg(&w_hh1[prow*30 + 2*kk + ks]);
                else {
                    float w13 = s*__ldg(&w_ih1[prow*13 + 12]);
                    val = (ks==0) ? w13 : (w13 - __half2float(__float2half_rn(w13)));
                }
                v[q] = val;
            }
            Bf[ks][nf][0] = f2h2(v[0], v[1]);
            Bf[ks][nf][1] = f2h2(v[2], v[3]);
        }
    }

    // ---- addresses ----
    const uint32_t AstW = sm32(Ast + wid*(32*144));
    uint32_t stH[2], stL[2];
    #pragma unroll
    for (int mh=0; mh<2; mh++){
        uint32_t r = AstW + (uint32_t)((mh*16 + rowA)*144 + p*32);
        stH[mh] = r; stL[mh] = r + 64;
    }
    const int sel = lane >> 3;
    const uint32_t ldmB = AstW + (uint32_t)(((sel&1)*8 + (lane&7))*144 + (sel>>1)*16);

    const float* bptr0 = baseS + (wid*32 + rowA)*BASE_STRIDE;
    const float* bptr1 = bptr0 + 16*BASE_STRIDE;

    float c1[30], h1[30];
    #pragma unroll
    for (int i=0;i<30;i++){ c1[i]=0.f; h1[i]=0.f; }
    float h2[2]={0.f,0.f}, c2[2]={0.f,0.f};
    const float b2r[4] = {0.5f*b2[0], 0.5f*b2[1], b2[2], 0.5f*b2[3]};
    const float wh2[4] = {0.5f*w_hh2[0], 0.5f*w_hh2[1], w_hh2[2], 0.5f*w_hh2[3]};
    float *outp0, *outp1;
    {
        int s0 = blockIdx.x*128 + wid*32 + rowA;
        outp0 = out + (size_t)s0*120;
        outp1 = out + (size_t)(s0+16)*120;
    }

    // ---- time recurrence ----
    #pragma unroll 1
    for (int t=0; t<120; t++){
        const float av    = c_avg[t];
        const float avh_f = __half2float(__float2half_rn(av));

        // stage h(t-1) split-fp16 + av columns (per-warp private tile)
        __syncwarp();
        #pragma unroll
        for (int mh=0; mh<2; mh++){
            const float* hh = h1 + mh*15;
            float lo[15];
            #pragma unroll
            for (int i=0;i<15;i++) lo[i] = hh[i] - __half2float(__float2half_rn(hh[i]));
            uint32_t Ph[8], Pl[8];
            #pragma unroll
            for (int j=0;j<7;j++){ Ph[j]=f2h2(hh[2*j],hh[2*j+1]); Pl[j]=f2h2(lo[2*j],lo[2*j+1]); }
            Ph[7] = f2h2(hh[14], av);
            Pl[7] = f2h2(lo[14], (p==0) ? (av - avh_f) : 0.f);
            asm volatile("st.shared.v4.b32 [%0], {%1,%2,%3,%4};" :: "r"(stH[mh]),    "r"(Ph[0]),"r"(Ph[1]),"r"(Ph[2]),"r"(Ph[3]));
            asm volatile("st.shared.v4.b32 [%0], {%1,%2,%3,%4};" :: "r"(stH[mh]+16), "r"(Ph[4]),"r"(Ph[5]),"r"(Ph[6]),"r"(Ph[7]));
            asm volatile("st.shared.v4.b32 [%0], {%1,%2,%3,%4};" :: "r"(stL[mh]),    "r"(Pl[0]),"r"(Pl[1]),"r"(Pl[2]),"r"(Pl[3]));
            asm volatile("st.shared.v4.b32 [%0], {%1,%2,%3,%4};" :: "r"(stL[mh]+16), "r"(Pl[4]),"r"(Pl[5]),"r"(Pl[6]),"r"(Pl[7]));
        }
        __syncwarp();

        #pragma unroll
        for (int mh=0; mh<2; mh++){
            uint32_t A[4][4];
            #pragma unroll
            for (int ks=0; ks<4; ks++){
                asm volatile("ldmatrix.sync.aligned.m8n8.x4.shared.b16 {%0,%1,%2,%3}, [%4];"
                    : "=r"(A[ks][0]),"=r"(A[ks][1]),"=r"(A[ks][2]),"=r"(A[ks][3])
                    : "r"(ldmB + (uint32_t)(mh*(16*144) + ks*32)));
            }
            const float* bp = mh ? bptr1 : bptr0;
            #pragma unroll
            for (int nf=0; nf<15; nf++){
                float d0=0.f, d1=0.f, d2=0.f, d3=0.f;
                #pragma unroll
                for (int ks=0; ks<4; ks++){
                    asm volatile("mma.sync.aligned.m16n8k16.row.col.f32.f16.f16.f32 "
                        "{%0,%1,%2,%3}, {%4,%5,%6,%7}, {%8,%9}, {%0,%1,%2,%3};"
                        : "+f"(d0),"+f"(d1),"+f"(d2),"+f"(d3)
                        : "r"(A[ks][0]),"r"(A[ks][1]),"r"(A[ks][2]),"r"(A[ks][3]),
                          "r"(Bf[ks&1][nf][0]),"r"(Bf[ks&1][nf][1]));
                }
                // pair exchange (xor 1): even-tg lane keeps row g (i,f), gets (g,o);
                // odd-tg lane keeps row g+8 (g,o), gets (i,f)
                float v0 = rsel ? d0 : d2;
                float v1 = rsel ? d1 : d3;
                float x0 = __shfl_xor_sync(0xFFFFFFFFu, v0, 1);
                float x1 = __shfl_xor_sync(0xFFFFFFFFu, v1, 1);
                float ii = rsel ? x0 : d0;
                float ff = rsel ? x1 : d1;
                float gG = rsel ? d2 : x0;
                float oo = rsel ? d3 : x1;
                float4 bs = *(const float4*)(bp + (2*nf + p)*4);
                float gi_ = ii + bs.x, gf_ = ff + bs.y, gg_ = gG + bs.z, go_ = oo + bs.w;
                const int idx = mh*15 + nf;
                float cc = fmaf(sig_h(gf_), c1[idx], sig_h(gi_)*tanhfast(gg_));
                c1[idx] = cc;
                h1[idx] = sig_h(go_)*tanhfast(cc);
            }
        }

        // ---- layer 2 (partials over own parity units, xor-2 reduce) ----
        {
            float sA[4]={0,0,0,0}, sB[4]={0,0,0,0};
            #pragma unroll
            for (int nf=0; nf<15; nf++){
                float4 w = w2S[2*nf + p];
                float hA = h1[nf], hB = h1[15+nf];
                sA[0]=fmaf(w.x,hA,sA[0]); sA[1]=fmaf(w.y,hA,sA[1]);
                sA[2]=fmaf(w.z,hA,sA[2]); sA[3]=fmaf(w.w,hA,sA[3]);
                sB[0]=fmaf(w.x,hB,sB[0]); sB[1]=fmaf(w.y,hB,sB[1]);
                sB[2]=fmaf(w.z,hB,sB[2]); sB[3]=fmaf(w.w,hB,sB[3]);
            }
            #pragma unroll
            for (int k=0;k<4;k++){
                sA[k] += __shfl_xor_sync(0xFFFFFFFFu, sA[k], 2);
                sB[k] += __shfl_xor_sync(0xFFFFFFFFu, sB[k], 2);
            }
            #pragma unroll
            for (int si=0; si<2; si++){
                const float* s = si ? sB : sA;
                float gi_ = s[0] + fmaf(wh2[0], h2[si], b2r[0]);
                float gf_ = s[1] + fmaf(wh2[1], h2[si], b2r[1]);
                float gg_ = s[2] + fmaf(wh2[2], h2[si], b2r[2]);
                float go_ = s[3] + fmaf(wh2[3], h2[si], b2r[3]);
                float cc = fmaf(sig_h(gf_), c2[si], sig_h(gi_)*tanhfast(gg_));
                c2[si] = cc;
                h2[si] = sig_h(go_)*tanhfast(cc);
            }
            if (p == 0){ outp0[t] = h2[0]; outp1[t] = h2[1]; }
        }
    }
}

extern "C" void kernel_launch(void* const* d_in, const int* in_sizes, int n_in,
                              void* d_out, int out_size)
{
    const float* features = (const float*)d_in[0];
    const float* w_ih1    = (const float*)d_in[1];
    const float* w_hh1    = (const float*)d_in[2];
    const float* b1       = (const float*)d_in[3];
    const float* w_ih2    = (const float*)d_in[4];
    const float* w_hh2    = (const float*)d_in[5];
    const float* b2       = (const float*)d_in[6];
    float* out = (float*)d_out;

    cudaFuncSetAttribute(lstm_mma_kernel,
                         cudaFuncAttributeMaxDynamicSharedMemorySize, SMEM_BYTES);
    lstm_mma_kernel<<<256, 128, SMEM_BYTES>>>(features, w_ih1, w_hh1, b1,
                                              w_ih2, w_hh2, b2, out);
}

// round 16
// speedup vs baseline: 3.0323x; 1.4273x over previous
#include <cuda_runtime.h>
#include <cuda_fp16.h>
#include <cstdint>

#define DI __device__ __forceinline__

// Fixed average-trace buffer (length 120) from the reference module
__constant__ float c_avg[120] = {
 0.0256f,0.0823f,0.1157f,0.1315f,0.1366f,0.1369f,0.1347f,0.1308f,0.1259f,0.1205f,
 0.1146f,0.1086f,0.1028f,0.0970f,0.0913f,0.0858f,0.0805f,0.0756f,0.0708f,0.0664f,
 0.0623f,0.0584f,0.0549f,0.0515f,0.0485f,0.0456f,0.0429f,0.0404f,0.0381f,0.0360f,
 0.0340f,0.0321f,0.0304f,0.0287f,0.0272f,0.0258f,0.0245f,0.0233f,0.0222f,0.0211f,
 0.0201f,0.0191f,0.0182f,0.0173f,0.0165f,0.0158f,0.0150f,0.0143f,0.0137f,0.0130f,
 0.0125f,0.0119f,0.0114f,0.0108f,0.0104f,0.0099f,0.0095f,0.0091f,0.0087f,0.0083f,
 0.0080f,0.0077f,0.0074f,0.0071f,0.0068f,0.0065f,0.0062f,0.0060f,0.0058f,0.0055f,
 0.0053f,0.0050f,0.0049f,0.0047f,0.0045f,0.0044f,0.0042f,0.0040f,0.0039f,0.0038f,
 0.0036f,0.0034f,0.0033f,0.0032f,0.0031f,0.0030f,0.0029f,0.0028f,0.0027f,0.0026f,
 0.0025f,0.0024f,0.0023f,0.0022f,0.0021f,0.0021f,0.0020f,0.0019f,0.0018f,0.0018f,
 0.0017f,0.0017f,0.0016f,0.0016f,0.0015f,0.0015f,0.0014f,0.0014f,0.0013f,0.0013f,
 0.0013f,0.0012f,0.0012f,0.0011f,0.0011f,0.0011f,0.0010f,0.0010f,0.0010f,0.0009f
};

DI float tanhfast(float x){ float y; asm("tanh.approx.f32 %0, %1;" : "=f"(y) : "f"(x)); return y; }
DI float sig_h(float xh){ return fmaf(tanhfast(xh), 0.5f, 0.5f); }   // arg pre-halved
DI uint32_t f2h2(float lo, float hi){
    __half2 h = __floats2half2_rn(lo, hi);
    return *reinterpret_cast<uint32_t*>(&h);
}
DI float hi16(float x){ return __half2float(__float2half_rn(x)); }
DI uint32_t sm32(const void* p){ return (uint32_t)__cvta_generic_to_shared(p); }
DI void barp(int id){ asm volatile("bar.sync %0, %1;" :: "r"(id), "r"(64) : "memory"); }

// ---- SMEM layout (bytes). CTA = 128 threads = 2 warp-pairs, 64 seqs. ----
#define BASE_STRIDE 124
#define OFF_BASE 0                    // f32 base[64 seq][124]      : 31744
#define OFF_W2   31744                // float4 w2S[30]             : 480 (pad)
#define OFF_PBUF 32256                // float4 pbuf[2pair][2w][32] : 2048
#define OFF_AST  34304                // 2 pair tiles: 32r x 144B   : 9216
#define SMEM_BYTES 43520

__global__ __launch_bounds__(128, 4)
void lstm_mma_kernel(const float* __restrict__ features,
                     const float* __restrict__ w_ih1,
                     const float* __restrict__ w_hh1,
                     const float* __restrict__ b1,
                     const float* __restrict__ w_ih2,
                     const float* __restrict__ w_hh2,
                     const float* __restrict__ b2,
                     float* __restrict__ out)
{
    extern __shared__ char smraw[];
    float*  baseS = (float*)(smraw + OFF_BASE);
    float4* w2S   = (float4*)(smraw + OFF_W2);
    float4* pbuf  = (float4*)(smraw + OFF_PBUF);
    char*   Ast   = smraw + OFF_AST;

    const int tid  = threadIdx.x;
    const int wid  = tid >> 5, lane = tid & 31;
    const int pairId = wid >> 1, w = wid & 1;
    const int g = lane >> 2, tg = lane & 3;
    const int p = tg >> 1, rsel = tg & 1;
    const int rowA = g + 8*rsel;
    const int nfc = 8 - w;               // warp0: nf 0..7, warp1: nf 8..14
    const int nf0 = w*8;
    const int barId = 1 + pairId;

    // ---- per-seq base (2 threads/seq: 15 units each), prescaled i,f,o x0.5 ----
    {
        int sx = tid & 63, uh = tid >> 6;
        int seq = blockIdx.x*64 + sx;
        const float4* fp = (const float4*)features + (size_t)seq*3;
        float4 fa=fp[0], fb=fp[1], fc=fp[2];
        float f[12] = {fa.x,fa.y,fa.z,fa.w, fb.x,fb.y,fb.z,fb.w, fc.x,fc.y,fc.z,fc.w};
        float* dst = baseS + sx*BASE_STRIDE;
        #pragma unroll 1
        for (int u = uh*15; u < uh*15+15; u++){
            float4 bs; float* bv = &bs.x;
            #pragma unroll
            for (int gg=0; gg<4; gg++){
                int row = gg*30 + u;
                float s = __ldg(&b1[row]);
                #pragma unroll
                for (int ff=0; ff<12; ff++) s = fmaf(__ldg(&w_ih1[row*13+ff]), f[ff], s);
                bv[gg] = (gg==2) ? s : 0.5f*s;
            }
            *(float4*)(dst + u*4) = bs;
        }
    }
    if (tid < 30)
        w2S[tid] = make_float4(0.5f*w_ih2[tid], 0.5f*w_ih2[30+tid],
                               w_ih2[60+tid],   0.5f*w_ih2[90+tid]);
    __syncthreads();

    // ---- B fragments (this warp's nf range only) ----
    uint32_t Bf[2][8][2];
    #pragma unroll
    for (int ks=0; ks<2; ks++){
        #pragma unroll
        for (int i=0; i<8; i++){
            if (i < nfc){
                int nf = nf0+i, n = nf*8 + g, u = n>>2, g4 = n&3;
                float s = (g4==2) ? 1.0f : 0.5f;
                int prow = g4*30 + u;
                float v[4];
                #pragma unroll
                for (int q=0; q<4; q++){
                    int kk = tg*2 + (q&1) + (q>>1)*8;
                    float val;
                    if (kk < 15) val = s*__ldg(&w_hh1[prow*30 + 2*kk + ks]);
                    else {
                        float w13 = s*__ldg(&w_ih1[prow*13 + 12]);
                        val = (ks==0) ? w13 : (w13 - hi16(w13));
                    }
                    v[q] = val;
                }
                Bf[ks][i][0] = f2h2(v[0], v[1]);
                Bf[ks][i][1] = f2h2(v[2], v[3]);
            } else { Bf[ks][i][0] = 0u; Bf[ks][i][1] = 0u; }
        }
    }

    // ---- addresses ----
    const uint32_t AstW = sm32(Ast + pairId*4608);
    uint32_t stH[2];
    #pragma unroll
    for (int mh=0; mh<2; mh++)
        stH[mh] = AstW + (uint32_t)((mh*16 + rowA)*144 + p*32 + w*16);
    const int sel = lane >> 3;
    const uint32_t ldmB = AstW + (uint32_t)(((sel&1)*8 + (lane&7))*144 + (sel>>1)*16);
    const float* bp0 = baseS + (pairId*32 + rowA)*BASE_STRIDE;
    const float* bp1 = bp0 + 16*BASE_STRIDE;

    float c1[16], h1[16];
    #pragma unroll
    for (int i=0;i<16;i++){ c1[i]=0.f; h1[i]=0.f; }
    float h2[2]={0.f,0.f}, c2[2]={0.f,0.f};
    const float b2r[4] = {0.5f*b2[0], 0.5f*b2[1], b2[2], 0.5f*b2[3]};
    const float wh2[4] = {0.5f*w_hh2[0], 0.5f*w_hh2[1], w_hh2[2], 0.5f*w_hh2[3]};
    const bool finLane = (w==1) && (tg<2);   // warp1 finishes layer 2 (it has 7 nf)
    const int seqF = blockIdx.x*64 + pairId*32 + rowA;
    float* outp0 = out + (size_t)seqF*120;
    float* outp1 = outp0 + 16*120;

    // ---- initial staging: h(-1)=0 + av(0) columns ----
    {
        float av0 = c_avg[0];
        uint32_t z = 0u;
        uint32_t P3 = (w==1) ? f2h2(0.f, av0) : 0u;
        uint32_t L3 = (w==1) ? f2h2(0.f, (p==0) ? (av0 - hi16(av0)) : 0.f) : 0u;
        #pragma unroll
        for (int mh=0; mh<2; mh++){
            asm volatile("st.shared.v4.b32 [%0], {%1,%2,%3,%4};" :: "r"(stH[mh]),    "r"(z),"r"(z),"r"(z),"r"(P3));
            asm volatile("st.shared.v4.b32 [%0], {%1,%2,%3,%4};" :: "r"(stH[mh]+64), "r"(z),"r"(z),"r"(z),"r"(L3));
        }
    }
    barp(barId);

    // ---- time recurrence ----
    #pragma unroll 1
    for (int t=0; t<120; t++){
        // ======== Phase A: read tile (h(t-1)), MMA, cell update; finish L2(t-1) ========
        if (t > 0 && finLane){
            float4 q0 = pbuf[(pairId*2+0)*32 + rowA];
            float4 r0 = pbuf[(pairId*2+1)*32 + rowA];
            float4 q1 = pbuf[(pairId*2+0)*32 + rowA + 16];
            float4 r1 = pbuf[(pairId*2+1)*32 + rowA + 16];
            #pragma unroll
            for (int si=0; si<2; si++){
                float4 qq = si ? q1 : q0, rr = si ? r1 : r0;
                float gi_ = qq.x + rr.x + fmaf(wh2[0], h2[si], b2r[0]);
                float gf_ = qq.y + rr.y + fmaf(wh2[1], h2[si], b2r[1]);
                float gg_ = qq.z + rr.z + fmaf(wh2[2], h2[si], b2r[2]);
                float go_ = qq.w + rr.w + fmaf(wh2[3], h2[si], b2r[3]);
                float cc = fmaf(sig_h(gf_), c2[si], sig_h(gi_)*tanhfast(gg_));
                c2[si] = cc;
                h2[si] = sig_h(go_)*tanhfast(cc);
            }
            outp0[t-1] = h2[0];
            outp1[t-1] = h2[1];
        }

        #pragma unroll
        for (int mh=0; mh<2; mh++){
            uint32_t A[4][4];
            #pragma unroll
            for (int ks=0; ks<4; ks++){
                asm volatile("ldmatrix.sync.aligned.m8n8.x4.shared.b16 {%0,%1,%2,%3}, [%4];"
                    : "=r"(A[ks][0]),"=r"(A[ks][1]),"=r"(A[ks][2]),"=r"(A[ks][3])
                    : "r"(ldmB + (uint32_t)(mh*(16*144) + ks*32)));
            }
            const float* bp = mh ? bp1 : bp0;
            #pragma unroll
            for (int i=0; i<8; i++){
                if (i >= nfc) break;
                float d0=0.f, d1=0.f, d2=0.f, d3=0.f;
                #pragma unroll
                for (int ks=0; ks<4; ks++){
                    asm volatile("mma.sync.aligned.m16n8k16.row.col.f32.f16.f16.f32 "
                        "{%0,%1,%2,%3}, {%4,%5,%6,%7}, {%8,%9}, {%0,%1,%2,%3};"
                        : "+f"(d0),"+f"(d1),"+f"(d2),"+f"(d3)
                        : "r"(A[ks][0]),"r"(A[ks][1]),"r"(A[ks][2]),"r"(A[ks][3]),
                          "r"(Bf[ks&1][i][0]),"r"(Bf[ks&1][i][1]));
                }
                float v0 = rsel ? d0 : d2;
                float v1 = rsel ? d1 : d3;
                float x0 = __shfl_xor_sync(0xFFFFFFFFu, v0, 1);
                float x1 = __shfl_xor_sync(0xFFFFFFFFu, v1, 1);
                float ii = rsel ? x0 : d0;
                float ff = rsel ? x1 : d1;
                float gG = rsel ? d2 : x0;
                float oo = rsel ? d3 : x1;
                float4 bs = *(const float4*)(bp + (2*(nf0+i) + p)*4);
                float gi_ = ii + bs.x, gf_ = ff + bs.y, gg_ = gG + bs.z, go_ = oo + bs.w;
                const int idx = mh*8 + i;
                float cc = fmaf(sig_h(gf_), c1[idx], sig_h(gi_)*tanhfast(gg_));
                c1[idx] = cc;
                h1[idx] = sig_h(go_)*tanhfast(cc);
            }
        }
        barp(barId);   // all tile + pbuf reads done -> writable

        // ======== Phase B: stage h(t) + av(t+1); layer-2 partials ========
        {
            const float avn = c_avg[(t < 119) ? (t+1) : 119];
            #pragma unroll
            for (int mh=0; mh<2; mh++){
                const float* hh = h1 + mh*8;
                float lo[8];
                #pragma unroll
                for (int i=0;i<8;i++) lo[i] = hh[i] - hi16(hh[i]);
                float v7h = (w==0) ? hh[7] : avn;
                float v7l = (w==0) ? lo[7] : ((p==0) ? (avn - hi16(avn)) : 0.f);
                uint32_t P0=f2h2(hh[0],hh[1]), P1=f2h2(hh[2],hh[3]),
                         P2=f2h2(hh[4],hh[5]), P3=f2h2(hh[6],v7h);
                uint32_t L0=f2h2(lo[0],lo[1]), L1=f2h2(lo[2],lo[3]),
                         L2=f2h2(lo[4],lo[5]), L3=f2h2(lo[6],v7l);
                asm volatile("st.shared.v4.b32 [%0], {%1,%2,%3,%4};" :: "r"(stH[mh]),    "r"(P0),"r"(P1),"r"(P2),"r"(P3));
                asm volatile("st.shared.v4.b32 [%0], {%1,%2,%3,%4};" :: "r"(stH[mh]+64), "r"(L0),"r"(L1),"r"(L2),"r"(L3));
            }
            // layer-2 partials over this warp's units
            float sA[4]={0,0,0,0}, sB[4]={0,0,0,0};
            #pragma unroll
            for (int i=0; i<8; i++){
                if (i >= nfc) break;
                float4 wv = w2S[2*(nf0+i) + p];
                float hA = h1[i], hB = h1[8+i];
                sA[0]=fmaf(wv.x,hA,sA[0]); sA[1]=fmaf(wv.y,hA,sA[1]);
                sA[2]=fmaf(wv.z,hA,sA[2]); sA[3]=fmaf(wv.w,hA,sA[3]);
                sB[0]=fmaf(wv.x,hB,sB[0]); sB[1]=fmaf(wv.y,hB,sB[1]);
                sB[2]=fmaf(wv.z,hB,sB[2]); sB[3]=fmaf(wv.w,hB,sB[3]);
            }
            #pragma unroll
            for (int k=0;k<4;k++){
                sA[k] += __shfl_xor_sync(0xFFFFFFFFu, sA[k], 2);
                sB[k] += __shfl_xor_sync(0xFFFFFFFFu, sB[k], 2);
            }
            if (tg < 2){
                pbuf[(pairId*2 + w)*32 + rowA]      = make_float4(sA[0],sA[1],sA[2],sA[3]);
                pbuf[(pairId*2 + w)*32 + rowA + 16] = make_float4(sB[0],sB[1],sB[2],sB[3]);
            }
        }
        barp(barId);   // tile(t) + pbuf(t) fully written
    }

    // ---- final layer-2 (t = 119) ----
    if (finLane){
        float4 q0 = pbuf[(pairId*2+0)*32 + rowA];
        float4 r0 = pbuf[(pairId*2+1)*32 + rowA];
        float4 q1 = pbuf[(pairId*2+0)*32 + rowA + 16];
        float4 r1 = pbuf[(pairId*2+1)*32 + rowA + 16];
        #pragma unroll
        for (int si=0; si<2; si++){
            float4 qq = si ? q1 : q0, rr = si ? r1 : r0;
            float gi_ = qq.x + rr.x + fmaf(wh2[0], h2[si], b2r[0]);
            float gf_ = qq.y + rr.y + fmaf(wh2[1], h2[si], b2r[1]);
            float gg_ = qq.z + rr.z + fmaf(wh2[2], h2[si], b2r[2]);
            float go_ = qq.w + rr.w + fmaf(wh2[3], h2[si], b2r[3]);
            float cc = fmaf(sig_h(gf_), c2[si], sig_h(gi_)*tanhfast(gg_));
            c2[si] = cc;
            h2[si] = sig_h(go_)*tanhfast(cc);
        }
        outp0[119] = h2[0];
        outp1[119] = h2[1];
    }
}

extern "C" void kernel_launch(void* const* d_in, const int* in_sizes, int n_in,
                              void* d_out, int out_size)
{
    const float* features = (const float*)d_in[0];
    const float* w_ih1    = (const float*)d_in[1];
    const float* w_hh1    = (const float*)d_in[2];
    const float* b1       = (const float*)d_in[3];
    const float* w_ih2    = (const float*)d_in[4];
    const float* w_hh2    = (const float*)d_in[5];
    const float* b2       = (const float*)d_in[6];
    float* out = (float*)d_out;

    cudaFuncSetAttribute(lstm_mma_kernel,
                         cudaFuncAttributeMaxDynamicSharedMemorySize, SMEM_BYTES);
    lstm_mma_kernel<<<512, 128, SMEM_BYTES>>>(features, w_ih1, w_hh1, b1,
                                              w_ih2, w_hh2, b2, out);
}

// round 17
// speedup vs baseline: 4.0876x; 1.3480x over previous
#include <cuda_runtime.h>
#include <cuda_fp16.h>
#include <cstdint>

#define DI __device__ __forceinline__

// Fixed average-trace buffer (length 120) from the reference module
__constant__ float c_avg[120] = {
 0.0256f,0.0823f,0.1157f,0.1315f,0.1366f,0.1369f,0.1347f,0.1308f,0.1259f,0.1205f,
 0.1146f,0.1086f,0.1028f,0.0970f,0.0913f,0.0858f,0.0805f,0.0756f,0.0708f,0.0664f,
 0.0623f,0.0584f,0.0549f,0.0515f,0.0485f,0.0456f,0.0429f,0.0404f,0.0381f,0.0360f,
 0.0340f,0.0321f,0.0304f,0.0287f,0.0272f,0.0258f,0.0245f,0.0233f,0.0222f,0.0211f,
 0.0201f,0.0191f,0.0182f,0.0173f,0.0165f,0.0158f,0.0150f,0.0143f,0.0137f,0.0130f,
 0.0125f,0.0119f,0.0114f,0.0108f,0.0104f,0.0099f,0.0095f,0.0091f,0.0087f,0.0083f,
 0.0080f,0.0077f,0.0074f,0.0071f,0.0068f,0.0065f,0.0062f,0.0060f,0.0058f,0.0055f,
 0.0053f,0.0050f,0.0049f,0.0047f,0.0045f,0.0044f,0.0042f,0.0040f,0.0039f,0.0038f,
 0.0036f,0.0034f,0.0033f,0.0032f,0.0031f,0.0030f,0.0029f,0.0028f,0.0027f,0.0026f,
 0.0025f,0.0024f,0.0023f,0.0022f,0.0021f,0.0021f,0.0020f,0.0019f,0.0018f,0.0018f,
 0.0017f,0.0017f,0.0016f,0.0016f,0.0015f,0.0015f,0.0014f,0.0014f,0.0013f,0.0013f,
 0.0013f,0.0012f,0.0012f,0.0011f,0.0011f,0.0011f,0.0010f,0.0010f,0.0010f,0.0009f
};

DI float tanhfast(float x){ float y; asm("tanh.approx.f32 %0, %1;" : "=f"(y) : "f"(x)); return y; }
DI float sig_h(float xh){ return fmaf(tanhfast(xh), 0.5f, 0.5f); }   // arg pre-halved
DI uint32_t f2h2(float lo, float hi){
    __half2 h = __floats2half2_rn(lo, hi);
    return *reinterpret_cast<uint32_t*>(&h);
}
DI float hi16(float x){ return __half2float(__float2half_rn(x)); }
DI uint32_t sm32(const void* p){ return (uint32_t)__cvta_generic_to_shared(p); }
DI void barp(int id){ asm volatile("bar.sync %0, %1;" :: "r"(id), "r"(64) : "memory"); }

// ---- SMEM layout (bytes). CTA = 128 threads = 2 warp-pairs, 64 seqs. ----
// baseS: 2 pair-blocks of [32 rows][32 np] float4, np XOR-swizzled by sig2(row)
// Ast:   2 pair tiles of 32 rows x 128B, 16B-chunk XOR-swizzled by sig(row)
#define OFF_BASE 0          // 32768
#define OFF_W2   32768      // 512
#define OFF_PBUF 33280      // 2048
#define OFF_AST  35328      // 8192
#define SMEM_BYTES 43520

__global__ __launch_bounds__(128, 4)
void lstm_mma_kernel(const float* __restrict__ features,
                     const float* __restrict__ w_ih1,
                     const float* __restrict__ w_hh1,
                     const float* __restrict__ b1,
                     const float* __restrict__ w_ih2,
                     const float* __restrict__ w_hh2,
                     const float* __restrict__ b2,
                     float* __restrict__ out)
{
    extern __shared__ char smraw[];
    float4* baseF = (float4*)(smraw + OFF_BASE);
    float4* w2S   = (float4*)(smraw + OFF_W2);
    float4* pbuf  = (float4*)(smraw + OFF_PBUF);
    char*   Ast   = smraw + OFF_AST;

    const int tid  = threadIdx.x;
    const int wid  = tid >> 5, lane = tid & 31;
    const int pairId = wid >> 1, w = wid & 1;
    const int g = lane >> 2, tg = lane & 3;
    const int p = tg >> 1, rsel = tg & 1;
    const int rowA = g + 8*rsel;
    const int nfc = 8 - w;               // warp0: nf 0..7, warp1: nf 8..14
    const int nf0 = w*8;
    const int barId = 1 + pairId;

    // swizzle constants for this lane
    const int sig  = g ^ (rsel << 2);                       // staging tile chunk swizzle
    const int sig2 = 2*((g & 1) | (rsel << 1));             // base np swizzle

    // ---- per-seq base (2 threads/seq: 15 units each), prescaled i,f,o x0.5 ----
    {
        int sx = tid & 63, uh = tid >> 6;
        int seq = blockIdx.x*64 + sx;
        int row = sx & 31;
        int s2w = 2*((row & 1) | (((row >> 3) & 1) << 1));
        int bidx = (sx >> 5)*1024 + row*32;
        const float4* fp = (const float4*)features + (size_t)seq*3;
        float4 fa=fp[0], fb=fp[1], fc=fp[2];
        float f[12] = {fa.x,fa.y,fa.z,fa.w, fb.x,fb.y,fb.z,fb.w, fc.x,fc.y,fc.z,fc.w};
        #pragma unroll 1
        for (int u = uh*15; u < uh*15+15; u++){
            float4 bs; float* bv = &bs.x;
            #pragma unroll
            for (int gg=0; gg<4; gg++){
                int row1 = gg*30 + u;
                float s = __ldg(&b1[row1]);
                #pragma unroll
                for (int ff=0; ff<12; ff++) s = fmaf(__ldg(&w_ih1[row1*13+ff]), f[ff], s);
                bv[gg] = (gg==2) ? s : 0.5f*s;
            }
            baseF[bidx + (u ^ s2w)] = bs;
        }
    }
    if (tid < 30)
        w2S[tid] = make_float4(0.5f*w_ih2[tid], 0.5f*w_ih2[30+tid],
                               w_ih2[60+tid],   0.5f*w_ih2[90+tid]);
    __syncthreads();

    // ---- B fragments (this warp's nf range only) ----
    uint32_t Bf[2][8][2];
    #pragma unroll
    for (int ks=0; ks<2; ks++){
        #pragma unroll
        for (int i=0; i<8; i++){
            if (i < nfc){
                int nf = nf0+i, n = nf*8 + g, u = n>>2, g4 = n&3;
                float s = (g4==2) ? 1.0f : 0.5f;
                int prow = g4*30 + u;
                float v[4];
                #pragma unroll
                for (int q=0; q<4; q++){
                    int kk = tg*2 + (q&1) + (q>>1)*8;
                    float val;
                    if (kk < 15) val = s*__ldg(&w_hh1[prow*30 + 2*kk + ks]);
                    else {
                        float w13 = s*__ldg(&w_ih1[prow*13 + 12]);
                        val = (ks==0) ? w13 : (w13 - hi16(w13));
                    }
                    v[q] = val;
                }
                Bf[ks][i][0] = f2h2(v[0], v[1]);
                Bf[ks][i][1] = f2h2(v[2], v[3]);
            } else { Bf[ks][i][0] = 0u; Bf[ks][i][1] = 0u; }
        }
    }

    // ---- addresses ----
    const uint32_t AstW = sm32(Ast + pairId*4096);
    const int lcH = 2*p + w;             // logical hi chunk
    uint32_t stH[2], stL[2];
    #pragma unroll
    for (int mh=0; mh<2; mh++){
        uint32_t rb = AstW + (uint32_t)((mh*16 + rowA)*128);
        stH[mh] = rb + (uint32_t)((lcH       ^ sig)*16);
        stL[mh] = rb + (uint32_t)(((lcH + 4) ^ sig)*16);
    }
    const int sel = lane >> 3;
    const int sel2 = sel >> 1;
    const int sigL = (lane & 7) ^ ((sel & 1) << 2);
    const uint32_t ldmRow = AstW + (uint32_t)((((sel&1)*8 + (lane&7)))*128);
    // base read index root (float4 units)
    const int bIdx0 = pairId*1024 + rowA*32;

    float c1[16], h1[16];
    #pragma unroll
    for (int i=0;i<16;i++){ c1[i]=0.f; h1[i]=0.f; }
    float h2[2]={0.f,0.f}, c2[2]={0.f,0.f};
    const float b2r[4] = {0.5f*b2[0], 0.5f*b2[1], b2[2], 0.5f*b2[3]};
    const float wh2[4] = {0.5f*w_hh2[0], 0.5f*w_hh2[1], w_hh2[2], 0.5f*w_hh2[3]};
    const bool finLane = (w==1) && (tg<2);   // warp1 finishes layer 2 (it has 7 nf)
    const int seqF = blockIdx.x*64 + pairId*32 + rowA;
    float* outp0 = out + (size_t)seqF*120;
    float* outp1 = outp0 + 16*120;

    // ---- initial staging: h(-1)=0 + av(0) columns ----
    {
        float av0 = c_avg[0];
        uint32_t z = 0u;
        uint32_t P3 = (w==1) ? f2h2(0.f, av0) : 0u;
        uint32_t L3 = (w==1) ? f2h2(0.f, (p==0) ? (av0 - hi16(av0)) : 0.f) : 0u;
        #pragma unroll
        for (int mh=0; mh<2; mh++){
            asm volatile("st.shared.v4.b32 [%0], {%1,%2,%3,%4};" :: "r"(stH[mh]), "r"(z),"r"(z),"r"(z),"r"(P3));
            asm volatile("st.shared.v4.b32 [%0], {%1,%2,%3,%4};" :: "r"(stL[mh]), "r"(z),"r"(z),"r"(z),"r"(L3));
        }
    }
    barp(barId);

    // ---- time recurrence ----
    #pragma unroll 1
    for (int t=0; t<120; t++){
        // ======== Phase A: MMA on h(t-1); cell update; finish L2(t-1) ========
        if (t > 0 && finLane){
            float4 q0 = pbuf[(pairId*2+0)*32 + rowA];
            float4 r0 = pbuf[(pairId*2+1)*32 + rowA];
            float4 q1 = pbuf[(pairId*2+0)*32 + rowA + 16];
            float4 r1 = pbuf[(pairId*2+1)*32 + rowA + 16];
            #pragma unroll
            for (int si=0; si<2; si++){
                float4 qq = si ? q1 : q0, rr = si ? r1 : r0;
                float gi_ = qq.x + rr.x + fmaf(wh2[0], h2[si], b2r[0]);
                float gf_ = qq.y + rr.y + fmaf(wh2[1], h2[si], b2r[1]);
                float gg_ = qq.z + rr.z + fmaf(wh2[2], h2[si], b2r[2]);
                float go_ = qq.w + rr.w + fmaf(wh2[3], h2[si], b2r[3]);
                float cc = fmaf(sig_h(gf_), c2[si], sig_h(gi_)*tanhfast(gg_));
                c2[si] = cc;
                h2[si] = sig_h(go_)*tanhfast(cc);
            }
            outp0[t-1] = h2[0];
            outp1[t-1] = h2[1];
        }

        #pragma unroll
        for (int mh=0; mh<2; mh++){
            uint32_t A[4][4];
            #pragma unroll
            for (int ks=0; ks<4; ks++){
                uint32_t ad = ldmRow + (uint32_t)(mh*2048 + ((2*ks + sel2) ^ sigL)*16);
                asm volatile("ldmatrix.sync.aligned.m8n8.x4.shared.b16 {%0,%1,%2,%3}, [%4];"
                    : "=r"(A[ks][0]),"=r"(A[ks][1]),"=r"(A[ks][2]),"=r"(A[ks][3])
                    : "r"(ad));
            }
            const int bI = bIdx0 + mh*512;
            #pragma unroll
            for (int i=0; i<8; i++){
                if (i >= nfc) break;
                float d0=0.f, d1=0.f, d2=0.f, d3=0.f;
                #pragma unroll
                for (int ks=0; ks<4; ks++){
                    asm volatile("mma.sync.aligned.m16n8k16.row.col.f32.f16.f16.f32 "
                        "{%0,%1,%2,%3}, {%4,%5,%6,%7}, {%8,%9}, {%0,%1,%2,%3};"
                        : "+f"(d0),"+f"(d1),"+f"(d2),"+f"(d3)
                        : "r"(A[ks][0]),"r"(A[ks][1]),"r"(A[ks][2]),"r"(A[ks][3]),
                          "r"(Bf[ks&1][i][0]),"r"(Bf[ks&1][i][1]));
                }
                float v0 = rsel ? d0 : d2;
                float v1 = rsel ? d1 : d3;
                float x0 = __shfl_xor_sync(0xFFFFFFFFu, v0, 1);
                float x1 = __shfl_xor_sync(0xFFFFFFFFu, v1, 1);
                float ii = rsel ? x0 : d0;
                float ff = rsel ? x1 : d1;
                float gG = rsel ? d2 : x0;
                float oo = rsel ? d3 : x1;
                float4 bs = baseF[bI + ((2*(nf0+i) + p) ^ sig2)];
                float gi_ = ii + bs.x, gf_ = ff + bs.y, gg_ = gG + bs.z, go_ = oo + bs.w;
                const int idx = mh*8 + i;
                float cc = fmaf(sig_h(gf_), c1[idx], sig_h(gi_)*tanhfast(gg_));
                c1[idx] = cc;
                h1[idx] = sig_h(go_)*tanhfast(cc);
            }
        }
        barp(barId);   // all tile + pbuf reads done -> writable

        // ======== Phase B: stage h(t) + av(t+1); layer-2 partials ========
        {
            const float avn = c_avg[(t < 119) ? (t+1) : 119];
            #pragma unroll
            for (int mh=0; mh<2; mh++){
                const float* hh = h1 + mh*8;
                float lo[8];
                #pragma unroll
                for (int i=0;i<8;i++) lo[i] = hh[i] - hi16(hh[i]);
                float v7h = (w==0) ? hh[7] : avn;
                float v7l = (w==0) ? lo[7] : ((p==0) ? (avn - hi16(avn)) : 0.f);
                uint32_t P0=f2h2(hh[0],hh[1]), P1=f2h2(hh[2],hh[3]),
                         P2=f2h2(hh[4],hh[5]), P3=f2h2(hh[6],v7h);
                uint32_t L0=f2h2(lo[0],lo[1]), L1=f2h2(lo[2],lo[3]),
                         L2=f2h2(lo[4],lo[5]), L3=f2h2(lo[6],v7l);
                asm volatile("st.shared.v4.b32 [%0], {%1,%2,%3,%4};" :: "r"(stH[mh]), "r"(P0),"r"(P1),"r"(P2),"r"(P3));
                asm volatile("st.shared.v4.b32 [%0], {%1,%2,%3,%4};" :: "r"(stL[mh]), "r"(L0),"r"(L1),"r"(L2),"r"(L3));
            }
            // layer-2 partials over this warp's units
            float sA[4]={0,0,0,0}, sB[4]={0,0,0,0};
            #pragma unroll
            for (int i=0; i<8; i++){
                if (i >= nfc) break;
                float4 wv = w2S[2*(nf0+i) + p];
                float hA = h1[i], hB = h1[8+i];
                sA[0]=fmaf(wv.x,hA,sA[0]); sA[1]=fmaf(wv.y,hA,sA[1]);
                sA[2]=fmaf(wv.z,hA,sA[2]); sA[3]=fmaf(wv.w,hA,sA[3]);
                sB[0]=fmaf(wv.x,hB,sB[0]); sB[1]=fmaf(wv.y,hB,sB[1]);
                sB[2]=fmaf(wv.z,hB,sB[2]); sB[3]=fmaf(wv.w,hB,sB[3]);
            }
            #pragma unroll
            for (int k=0;k<4;k++){
                sA[k] += __shfl_xor_sync(0xFFFFFFFFu, sA[k], 2);
                sB[k] += __shfl_xor_sync(0xFFFFFFFFu, sB[k], 2);
            }
            if (tg < 2){
                pbuf[(pairId*2 + w)*32 + rowA]      = make_float4(sA[0],sA[1],sA[2],sA[3]);
                pbuf[(pairId*2 + w)*32 + rowA + 16] = make_float4(sB[0],sB[1],sB[2],sB[3]);
            }
        }
        barp(barId);   // tile(t) + pbuf(t) fully written
    }

    // ---- final layer-2 (t = 119) ----
    if (finLane){
        float4 q0 = pbuf[(pairId*2+0)*32 + rowA];
        float4 r0 = pbuf[(pairId*2+1)*32 + rowA];
        float4 q1 = pbuf[(pairId*2+0)*32 + rowA + 16];
        float4 r1 = pbuf[(pairId*2+1)*32 + rowA + 16];
        #pragma unroll
        for (int si=0; si<2; si++){
            float4 qq = si ? q1 : q0, rr = si ? r1 : r0;
            float gi_ = qq.x + rr.x + fmaf(wh2[0], h2[si], b2r[0]);
            float gf_ = qq.y + rr.y + fmaf(wh2[1], h2[si], b2r[1]);
            float gg_ = qq.z + rr.z + fmaf(wh2[2], h2[si], b2r[2]);
            float go_ = qq.w + rr.w + fmaf(wh2[3], h2[si], b2r[3]);
            float cc = fmaf(sig_h(gf_), c2[si], sig_h(gi_)*tanhfast(gg_));
            c2[si] = cc;
            h2[si] = sig_h(go_)*tanhfast(cc);
        }
        outp0[119] = h2[0];
        outp1[119] = h2[1];
    }
}

extern "C" void kernel_launch(void* const* d_in, const int* in_sizes, int n_in,
                              void* d_out, int out_size)
{
    const float* features = (const float*)d_in[0];
    const float* w_ih1    = (const float*)d_in[1];
    const float* w_hh1    = (const float*)d_in[2];
    const float* b1       = (const float*)d_in[3];
    const float* w_ih2    = (const float*)d_in[4];
    const float* w_hh2    = (const float*)d_in[5];
    const float* b2       = (const float*)d_in[6];
    float* out = (float*)d_out;

    cudaFuncSetAttribute(lstm_mma_kernel,
                         cudaFuncAttributeMaxDynamicSharedMemorySize, SMEM_BYTES);
    lstm_mma_kernel<<<512, 128, SMEM_BYTES>>>(features, w_ih1, w_hh1, b1,
                                              w_ih2, w_hh2, b2, out);
}